// round 4
// baseline (speedup 1.0000x reference)
#include <cuda_runtime.h>
#include <cuda_bf16.h>

#define N_NODES 50000
#define N_EDGES 800000
#define IN_SIZE 1024
#define EMB 500

// Scratch (device globals: allocation-free per harness rules)
__device__ float g_h[(size_t)N_NODES * EMB];    // sigmoid(x@wenc^T+benc)
__device__ float g_h2[(size_t)N_NODES * EMB];   // h @ conv_weight
__device__ float g_agg[(size_t)N_NODES * EMB];  // h @ lin^T, then += scatter

// ---------------------------------------------------------------------------
// Tiled fp32 GEMM: C[M,N] = act(A[M,K] @ op(B) + bias)
//   BT=true : B stored [N,K] row-major, compute A @ B^T
//   BT=false: B stored [K,N] row-major, compute A @ B
// BM=BN=128, BK=8, 256 threads, 8x8 micro-tile per thread.
// ---------------------------------------------------------------------------
template <bool BT, bool BIAS, bool SIG>
__global__ __launch_bounds__(256) void sgemm(
    const float* __restrict__ A, const float* __restrict__ B,
    const float* __restrict__ bias, float* __restrict__ C,
    int M, int N, int K)
{
    __shared__ float As[8][128];
    __shared__ float Bs[8][128];

    const int tid = threadIdx.x;
    const int m0 = blockIdx.y * 128;
    const int n0 = blockIdx.x * 128;
    const int tx = tid & 15;   // n micro-tile
    const int ty = tid >> 4;   // m micro-tile

    // Load mapping for K-contiguous tiles (A always; B when BT)
    const int lrow = tid >> 1;          // 0..127
    const int lkq  = (tid & 1) * 4;     // 0 or 4
    // Load mapping for N-contiguous B (BT=false)
    const int bk_nt = tid >> 5;         // 0..7
    const int bn_nt = (tid & 31) * 4;   // 0..124*4

    float acc[8][8];
    #pragma unroll
    for (int i = 0; i < 8; i++)
        #pragma unroll
        for (int j = 0; j < 8; j++) acc[i][j] = 0.f;

    for (int k0 = 0; k0 < K; k0 += 8) {
        // ---- load A tile (transposed into As[k][m]) ----
        {
            const int gm = m0 + lrow;
            const int gk = k0 + lkq;
            float4 v = make_float4(0.f, 0.f, 0.f, 0.f);
            if (gm < M) {
                if (gk + 3 < K) {
                    v = *reinterpret_cast<const float4*>(&A[(long long)gm * K + gk]);
                } else {
                    float t[4] = {0.f, 0.f, 0.f, 0.f};
                    #pragma unroll
                    for (int i = 0; i < 4; i++)
                        if (gk + i < K) t[i] = A[(long long)gm * K + gk + i];
                    v = make_float4(t[0], t[1], t[2], t[3]);
                }
            }
            As[lkq + 0][lrow] = v.x; As[lkq + 1][lrow] = v.y;
            As[lkq + 2][lrow] = v.z; As[lkq + 3][lrow] = v.w;
        }
        // ---- load B tile into Bs[k][n] ----
        if (BT) {
            const int gn = n0 + lrow;
            const int gk = k0 + lkq;
            float4 v = make_float4(0.f, 0.f, 0.f, 0.f);
            if (gn < N) {
                if (gk + 3 < K) {
                    v = *reinterpret_cast<const float4*>(&B[(long long)gn * K + gk]);
                } else {
                    float t[4] = {0.f, 0.f, 0.f, 0.f};
                    #pragma unroll
                    for (int i = 0; i < 4; i++)
                        if (gk + i < K) t[i] = B[(long long)gn * K + gk + i];
                    v = make_float4(t[0], t[1], t[2], t[3]);
                }
            }
            Bs[lkq + 0][lrow] = v.x; Bs[lkq + 1][lrow] = v.y;
            Bs[lkq + 2][lrow] = v.z; Bs[lkq + 3][lrow] = v.w;
        } else {
            const int gk = k0 + bk_nt;
            const int gn = n0 + bn_nt;
            float4 v = make_float4(0.f, 0.f, 0.f, 0.f);
            if (gk < K) {
                if (gn + 3 < N) {
                    v = *reinterpret_cast<const float4*>(&B[(long long)gk * N + gn]);
                } else {
                    float t[4] = {0.f, 0.f, 0.f, 0.f};
                    #pragma unroll
                    for (int i = 0; i < 4; i++)
                        if (gn + i < N) t[i] = B[(long long)gk * N + gn + i];
                    v = make_float4(t[0], t[1], t[2], t[3]);
                }
            }
            *reinterpret_cast<float4*>(&Bs[bk_nt][bn_nt]) = v;
        }
        __syncthreads();

        // ---- compute ----
        #pragma unroll
        for (int kk = 0; kk < 8; kk++) {
            const float4 a0 = *reinterpret_cast<const float4*>(&As[kk][ty * 8]);
            const float4 a1 = *reinterpret_cast<const float4*>(&As[kk][ty * 8 + 4]);
            const float4 b0 = *reinterpret_cast<const float4*>(&Bs[kk][tx * 8]);
            const float4 b1 = *reinterpret_cast<const float4*>(&Bs[kk][tx * 8 + 4]);
            const float a[8] = {a0.x, a0.y, a0.z, a0.w, a1.x, a1.y, a1.z, a1.w};
            const float b[8] = {b0.x, b0.y, b0.z, b0.w, b1.x, b1.y, b1.z, b1.w};
            #pragma unroll
            for (int i = 0; i < 8; i++)
                #pragma unroll
                for (int j = 0; j < 8; j++)
                    acc[i][j] = fmaf(a[i], b[j], acc[i][j]);
        }
        __syncthreads();
    }

    // ---- epilogue ----
    #pragma unroll
    for (int i = 0; i < 8; i++) {
        const int gm = m0 + ty * 8 + i;
        if (gm >= M) continue;
        #pragma unroll
        for (int j = 0; j < 8; j++) {
            const int gn = n0 + tx * 8 + j;
            if (gn >= N) continue;
            float v = acc[i][j];
            if (BIAS) v += bias[gn];
            if (SIG) v = 1.f / (1.f + expf(-v));
            C[(long long)gm * N + gn] = v;
        }
    }
}

// ---------------------------------------------------------------------------
// Edge scatter: agg[dst] += h2[src] * w  — one block per edge, vec4 atomics.
// ---------------------------------------------------------------------------
__global__ __launch_bounds__(128) void scatter_edges(
    const int* __restrict__ edge_index, const float* __restrict__ ew,
    const float* __restrict__ h2, float* __restrict__ agg)
{
    const int e = blockIdx.x;
    const int src = edge_index[e];
    const int dst = edge_index[N_EDGES + e];
    const float w = ew[e];
    const int c = threadIdx.x * 4;
    if (c < EMB) {  // EMB = 500 = 125 float4 chunks
        float4 v = *reinterpret_cast<const float4*>(&h2[(long long)src * EMB + c]);
        v.x *= w; v.y *= w; v.z *= w; v.w *= w;
        float* p = &agg[(long long)dst * EMB + c];
        asm volatile("red.global.add.v4.f32 [%0], {%1, %2, %3, %4};"
                     :: "l"(p), "f"(v.x), "f"(v.y), "f"(v.z), "f"(v.w)
                     : "memory");
    }
}

extern "C" void kernel_launch(void* const* d_in, const int* in_sizes, int n_in,
                              void* d_out, int out_size)
{
    const float* x           = (const float*)d_in[0];  // [N_NODES, IN_SIZE]
    const int*   edge_index  = (const int*)  d_in[1];  // [2, N_EDGES]
    const float* edge_weight = (const float*)d_in[2];  // [N_EDGES]
    const float* wenc        = (const float*)d_in[3];  // [EMB, IN_SIZE]
    const float* benc        = (const float*)d_in[4];  // [EMB]
    const float* wdec        = (const float*)d_in[5];  // [IN_SIZE, EMB]
    const float* bdec        = (const float*)d_in[6];  // [IN_SIZE]
    const float* conv_weight = (const float*)d_in[7];  // [EMB, EMB]
    const float* lin_weight  = (const float*)d_in[8];  // [EMB, EMB]
    float* out = (float*)d_out;                        // [N_NODES, IN_SIZE]

    float *h, *h2, *agg;
    cudaGetSymbolAddress((void**)&h, g_h);
    cudaGetSymbolAddress((void**)&h2, g_h2);
    cudaGetSymbolAddress((void**)&agg, g_agg);

    const dim3 blk(256);
    const int mt = (N_NODES + 127) / 128;  // 391

    // 1) h = sigmoid(x @ wenc^T + benc)       [BT, bias, sigmoid]
    {
        dim3 grid((EMB + 127) / 128, mt);
        sgemm<true, true, true><<<grid, blk>>>(x, wenc, benc, h,
                                               N_NODES, EMB, IN_SIZE);
    }
    // 2) h2 = h @ conv_weight                 [no-T, no bias]
    {
        dim3 grid((EMB + 127) / 128, mt);
        sgemm<false, false, false><<<grid, blk>>>(h, conv_weight, nullptr, h2,
                                                  N_NODES, EMB, EMB);
    }
    // 3) agg = h @ lin_weight^T               [BT, no bias] (root term init)
    {
        dim3 grid((EMB + 127) / 128, mt);
        sgemm<true, false, false><<<grid, blk>>>(h, lin_weight, nullptr, agg,
                                                 N_NODES, EMB, EMB);
    }
    // 4) agg += scatter(h2[src] * w -> dst)
    scatter_edges<<<N_EDGES, 128>>>(edge_index, edge_weight, h2, agg);
    // 5) out = agg @ wdec^T + bdec            [BT, bias]
    {
        dim3 grid((IN_SIZE + 127) / 128, mt);
        sgemm<true, true, false><<<grid, blk>>>(agg, wdec, bdec, out,
                                                N_NODES, IN_SIZE, EMB);
    }
}

// round 6
// speedup vs baseline: 1.6830x; 1.6830x over previous
#include <cuda_runtime.h>
#include <cuda_bf16.h>
#include <cstdint>

#define N_NODES 50000
#define N_EDGES 800000
#define IN_SIZE 1024
#define EMB 500
#define EMBP 512   // EMB padded to multiple of 32

// ---------------------------------------------------------------------------
// Scratch (device globals: allocation-free per harness rules)
// ---------------------------------------------------------------------------
__device__ __nv_bfloat16 g_xhi[(size_t)N_NODES * IN_SIZE];
__device__ __nv_bfloat16 g_xlo[(size_t)N_NODES * IN_SIZE];
__device__ __nv_bfloat16 g_hhi[(size_t)N_NODES * EMBP];
__device__ __nv_bfloat16 g_hlo[(size_t)N_NODES * EMBP];
__device__ float         g_h2[(size_t)N_NODES * EMB];
__device__ float         g_agg[(size_t)N_NODES * EMB];
__device__ __nv_bfloat16 g_agghi[(size_t)N_NODES * EMBP];
__device__ __nv_bfloat16 g_agglo[(size_t)N_NODES * EMBP];
// weight splits (B stored [N][Kp], row n = output feature, k contiguous)
__device__ __nv_bfloat16 g_wenchi[EMB * IN_SIZE],  g_wenclo[EMB * IN_SIZE];
__device__ __nv_bfloat16 g_convthi[EMB * EMBP],    g_convtlo[EMB * EMBP];
__device__ __nv_bfloat16 g_linhi[EMB * EMBP],      g_linlo[EMB * EMBP];
__device__ __nv_bfloat16 g_wdechi[IN_SIZE * EMBP], g_wdeclo[IN_SIZE * EMBP];

// ---------------------------------------------------------------------------
__device__ __forceinline__ void split2(float f, __nv_bfloat16& hi, __nv_bfloat16& lo) {
    hi = __float2bfloat16_rn(f);
    lo = __float2bfloat16_rn(f - __bfloat162float(hi));
}

// split x (no padding, IN_SIZE multiple of 4)
__global__ __launch_bounds__(256) void split_x_kernel(
    const float4* __restrict__ x, __nv_bfloat16* __restrict__ hi,
    __nv_bfloat16* __restrict__ lo, long long n4)
{
    long long i = (long long)blockIdx.x * blockDim.x + threadIdx.x;
    if (i >= n4) return;
    float4 v = x[i];
    __nv_bfloat16 h0, h1, h2, h3, l0, l1, l2, l3;
    split2(v.x, h0, l0); split2(v.y, h1, l1);
    split2(v.z, h2, l2); split2(v.w, h3, l3);
    __nv_bfloat162* ph = reinterpret_cast<__nv_bfloat162*>(hi) + i * 2;
    __nv_bfloat162* pl = reinterpret_cast<__nv_bfloat162*>(lo) + i * 2;
    ph[0] = __nv_bfloat162(h0, h1); ph[1] = __nv_bfloat162(h2, h3);
    pl[0] = __nv_bfloat162(l0, l1); pl[1] = __nv_bfloat162(l2, l3);
}

// split a weight matrix into [N][Kp] hi/lo with zero pad; TRANS reads src[k*N+n]
template <bool TRANS>
__global__ __launch_bounds__(256) void split_w_kernel(
    const float* __restrict__ src, __nv_bfloat16* __restrict__ hi,
    __nv_bfloat16* __restrict__ lo, int N, int K, int Kp)
{
    int idx = blockIdx.x * blockDim.x + threadIdx.x;
    if (idx >= N * Kp) return;
    int n = idx / Kp, k = idx - n * Kp;
    float v = 0.f;
    if (k < K) v = TRANS ? src[(long long)k * N + n] : src[(long long)n * K + k];
    split2(v, hi[idx], lo[idx]);
}

// split agg [M][EMB] fp32 -> [M][EMBP] hi/lo
__global__ __launch_bounds__(256) void split_agg_kernel(
    const float* __restrict__ agg, __nv_bfloat16* __restrict__ hi,
    __nv_bfloat16* __restrict__ lo)
{
    long long idx = (long long)blockIdx.x * blockDim.x + threadIdx.x;
    if (idx >= (long long)N_NODES * EMBP) return;
    int c = (int)(idx & (EMBP - 1));
    long long r = idx >> 9;  // EMBP = 512
    float v = (c < EMB) ? agg[r * EMB + c] : 0.f;
    split2(v, hi[idx], lo[idx]);
}

// ---------------------------------------------------------------------------
// bf16x3 split-precision GEMM on tensor cores (mma.sync m16n8k16)
// C[M,N] = act(A[M,K] @ B[N,K]^T + bias), A/B pre-split into bf16 hi/lo.
// BM=BN=128, BK=32, 256 threads = 8 warps (4 M x 2 N), warp tile 32x64.
// K must be a multiple of 32 (callers pass padded K; pads are zero).
// ---------------------------------------------------------------------------
#define KPAD 40  // smem halves per row (80B stride -> conflict-free ldmatrix)

__device__ __forceinline__ void ldsm4(uint32_t (&r)[4], uint32_t addr) {
    asm volatile("ldmatrix.sync.aligned.m8n8.x4.shared.b16 {%0,%1,%2,%3}, [%4];"
                 : "=r"(r[0]), "=r"(r[1]), "=r"(r[2]), "=r"(r[3]) : "r"(addr));
}
__device__ __forceinline__ void mma_bf16(float (&c)[4], const uint32_t (&a)[4],
                                         uint32_t b0, uint32_t b1) {
    asm volatile(
        "mma.sync.aligned.m16n8k16.row.col.f32.bf16.bf16.f32 "
        "{%0,%1,%2,%3}, {%4,%5,%6,%7}, {%8,%9}, {%0,%1,%2,%3};"
        : "+f"(c[0]), "+f"(c[1]), "+f"(c[2]), "+f"(c[3])
        : "r"(a[0]), "r"(a[1]), "r"(a[2]), "r"(a[3]), "r"(b0), "r"(b1));
}

template <bool PAIR, bool BIAS, bool SIG>
__global__ __launch_bounds__(256, 1) void bgemm(
    const __nv_bfloat16* __restrict__ Ahi, const __nv_bfloat16* __restrict__ Alo,
    int sA_, const __nv_bfloat16* __restrict__ Bhi,
    const __nv_bfloat16* __restrict__ Blo, int sB_,
    const float* __restrict__ bias,
    float* __restrict__ C, int sC,
    __nv_bfloat16* __restrict__ Chi, __nv_bfloat16* __restrict__ Clo, int sCp,
    int M, int N, int K)
{
    __shared__ __align__(16) __nv_bfloat16 sA[2][128][KPAD];
    __shared__ __align__(16) __nv_bfloat16 sB[2][128][KPAD];

    const int t = threadIdx.x;
    const int lane = t & 31;
    const int warp = t >> 5;
    const int wm = warp >> 1;   // 0..3
    const int wn = warp & 1;    // 0..1
    const int m0 = blockIdx.y * 128;
    const int n0 = blockIdx.x * 128;

    // gmem->smem mapping: thread t loads 16 halves of one row
    const int lrow = t >> 1;
    const int lc   = (t & 1) * 16;

    float acc[2][8][4];
    #pragma unroll
    for (int i = 0; i < 2; i++)
        #pragma unroll
        for (int j = 0; j < 8; j++)
            #pragma unroll
            for (int e = 0; e < 4; e++) acc[i][j][e] = 0.f;

    const int g = lane >> 3, r8 = lane & 7;

    for (int k0 = 0; k0 < K; k0 += 32) {
        // ---- load A/B tiles (hi & lo) ----
        {
            const int gr = m0 + lrow;
            const long long off = (long long)gr * sA_ + k0 + lc;
            uint4 h0 = {0,0,0,0}, h1 = {0,0,0,0}, l0 = {0,0,0,0}, l1 = {0,0,0,0};
            if (gr < M) {
                h0 = *reinterpret_cast<const uint4*>(Ahi + off);
                h1 = *reinterpret_cast<const uint4*>(Ahi + off + 8);
                l0 = *reinterpret_cast<const uint4*>(Alo + off);
                l1 = *reinterpret_cast<const uint4*>(Alo + off + 8);
            }
            *reinterpret_cast<uint4*>(&sA[0][lrow][lc])     = h0;
            *reinterpret_cast<uint4*>(&sA[0][lrow][lc + 8]) = h1;
            *reinterpret_cast<uint4*>(&sA[1][lrow][lc])     = l0;
            *reinterpret_cast<uint4*>(&sA[1][lrow][lc + 8]) = l1;
        }
        {
            const int gn = n0 + lrow;
            const long long off = (long long)gn * sB_ + k0 + lc;
            uint4 h0 = {0,0,0,0}, h1 = {0,0,0,0}, l0 = {0,0,0,0}, l1 = {0,0,0,0};
            if (gn < N) {
                h0 = *reinterpret_cast<const uint4*>(Bhi + off);
                h1 = *reinterpret_cast<const uint4*>(Bhi + off + 8);
                l0 = *reinterpret_cast<const uint4*>(Blo + off);
                l1 = *reinterpret_cast<const uint4*>(Blo + off + 8);
            }
            *reinterpret_cast<uint4*>(&sB[0][lrow][lc])     = h0;
            *reinterpret_cast<uint4*>(&sB[0][lrow][lc + 8]) = h1;
            *reinterpret_cast<uint4*>(&sB[1][lrow][lc])     = l0;
            *reinterpret_cast<uint4*>(&sB[1][lrow][lc + 8]) = l1;
        }
        __syncthreads();

        #pragma unroll
        for (int ks = 0; ks < 2; ks++) {
            const int kk = ks * 16;
            // A fragments: [hi/lo][mtile][4]
            uint32_t a[2][2][4];
            #pragma unroll
            for (int h = 0; h < 2; h++)
                #pragma unroll
                for (int mt = 0; mt < 2; mt++) {
                    const int row = wm * 32 + mt * 16 + (g & 1) * 8 + r8;
                    const int col = kk + (g >> 1) * 8;
                    ldsm4(a[h][mt],
                          (uint32_t)__cvta_generic_to_shared(&sA[h][row][col]));
                }
            // B fragments: [hi/lo][pgroup][4]  (pgroup = 2 n-tiles)
            uint32_t b[2][4][4];
            #pragma unroll
            for (int h = 0; h < 2; h++)
                #pragma unroll
                for (int p = 0; p < 4; p++) {
                    const int row = wn * 64 + p * 16 + (g >> 1) * 8 + r8;
                    const int col = kk + (g & 1) * 8;
                    ldsm4(b[h][p],
                          (uint32_t)__cvta_generic_to_shared(&sB[h][row][col]));
                }
            // 3-term split MMA: hi*hi + hi*lo + lo*hi
            #pragma unroll
            for (int mt = 0; mt < 2; mt++)
                #pragma unroll
                for (int p = 0; p < 4; p++)
                    #pragma unroll
                    for (int s = 0; s < 2; s++) {
                        const int nt = p * 2 + s;
                        const uint32_t bh0 = b[0][p][s * 2], bh1 = b[0][p][s * 2 + 1];
                        const uint32_t bl0 = b[1][p][s * 2], bl1 = b[1][p][s * 2 + 1];
                        mma_bf16(acc[mt][nt], a[0][mt], bh0, bh1);
                        mma_bf16(acc[mt][nt], a[0][mt], bl0, bl1);
                        mma_bf16(acc[mt][nt], a[1][mt], bh0, bh1);
                    }
        }
        __syncthreads();
    }

    // ---- epilogue ----
    const int rq = lane >> 2, cq = (lane & 3) * 2;
    #pragma unroll
    for (int mt = 0; mt < 2; mt++)
        #pragma unroll
        for (int nt = 0; nt < 8; nt++) {
            const int gr0 = m0 + wm * 32 + mt * 16 + rq;
            const int gc0 = n0 + wn * 64 + nt * 8 + cq;
            #pragma unroll
            for (int e = 0; e < 4; e++) {
                const int gm = gr0 + (e >> 1) * 8;
                const int gn = gc0 + (e & 1);
                if (gm >= M) continue;
                float v = acc[mt][nt][e];
                if (gn < N) {
                    if (BIAS) v += bias[gn];
                    if (SIG) v = 1.f / (1.f + expf(-v));
                } else {
                    v = 0.f;
                }
                if (PAIR) {
                    // padded bf16 hi/lo output (stride sCp covers gn up to 511)
                    __nv_bfloat16 hi, lo;
                    split2(v, hi, lo);
                    const long long o = (long long)gm * sCp + gn;
                    Chi[o] = hi; Clo[o] = lo;
                } else if (gn < N) {
                    C[(long long)gm * sC + gn] = v;
                }
            }
        }
}

// ---------------------------------------------------------------------------
// Edge scatter: agg[dst] += h2[src] * w  — one block per edge, vec4 atomics.
// ---------------------------------------------------------------------------
__global__ __launch_bounds__(128) void scatter_edges(
    const int* __restrict__ edge_index, const float* __restrict__ ew,
    const float* __restrict__ h2, float* __restrict__ agg)
{
    const int e = blockIdx.x;
    const int src = edge_index[e];
    const int dst = edge_index[N_EDGES + e];
    const float w = ew[e];
    const int c = threadIdx.x * 4;
    if (c < EMB) {
        float4 v = *reinterpret_cast<const float4*>(&h2[(long long)src * EMB + c]);
        v.x *= w; v.y *= w; v.z *= w; v.w *= w;
        float* p = &agg[(long long)dst * EMB + c];
        asm volatile("red.global.add.v4.f32 [%0], {%1, %2, %3, %4};"
                     :: "l"(p), "f"(v.x), "f"(v.y), "f"(v.z), "f"(v.w)
                     : "memory");
    }
}

// ---------------------------------------------------------------------------
extern "C" void kernel_launch(void* const* d_in, const int* in_sizes, int n_in,
                              void* d_out, int out_size)
{
    const float* x           = (const float*)d_in[0];
    const int*   edge_index  = (const int*)  d_in[1];
    const float* edge_weight = (const float*)d_in[2];
    const float* wenc        = (const float*)d_in[3];  // [EMB, IN_SIZE]
    const float* benc        = (const float*)d_in[4];
    const float* wdec        = (const float*)d_in[5];  // [IN_SIZE, EMB]
    const float* bdec        = (const float*)d_in[6];
    const float* conv_weight = (const float*)d_in[7];  // [EMB, EMB] (k, n)
    const float* lin_weight  = (const float*)d_in[8];  // [EMB, EMB] (n, k)
    float* out = (float*)d_out;

    __nv_bfloat16 *xhi, *xlo, *hhi, *hlo, *agghi, *agglo;
    __nv_bfloat16 *wenchi, *wenclo, *convthi, *convtlo, *linhi, *linlo, *wdechi, *wdeclo;
    float *h2, *agg;
    cudaGetSymbolAddress((void**)&xhi, g_xhi);     cudaGetSymbolAddress((void**)&xlo, g_xlo);
    cudaGetSymbolAddress((void**)&hhi, g_hhi);     cudaGetSymbolAddress((void**)&hlo, g_hlo);
    cudaGetSymbolAddress((void**)&agghi, g_agghi); cudaGetSymbolAddress((void**)&agglo, g_agglo);
    cudaGetSymbolAddress((void**)&h2, g_h2);       cudaGetSymbolAddress((void**)&agg, g_agg);
    cudaGetSymbolAddress((void**)&wenchi, g_wenchi);   cudaGetSymbolAddress((void**)&wenclo, g_wenclo);
    cudaGetSymbolAddress((void**)&convthi, g_convthi); cudaGetSymbolAddress((void**)&convtlo, g_convtlo);
    cudaGetSymbolAddress((void**)&linhi, g_linhi);     cudaGetSymbolAddress((void**)&linlo, g_linlo);
    cudaGetSymbolAddress((void**)&wdechi, g_wdechi);   cudaGetSymbolAddress((void**)&wdeclo, g_wdeclo);

    const int mt = (N_NODES + 127) / 128;  // 391

    // ---- prep: split inputs/weights into bf16 hi/lo ----
    {
        long long n4 = (long long)N_NODES * IN_SIZE / 4;
        split_x_kernel<<<(unsigned)((n4 + 255) / 256), 256>>>(
            (const float4*)x, xhi, xlo, n4);
    }
    split_w_kernel<false><<<(EMB * IN_SIZE + 255) / 256, 256>>>(
        wenc, wenchi, wenclo, EMB, IN_SIZE, IN_SIZE);
    split_w_kernel<true><<<(EMB * EMBP + 255) / 256, 256>>>(
        conv_weight, convthi, convtlo, EMB, EMB, EMBP);
    split_w_kernel<false><<<(EMB * EMBP + 255) / 256, 256>>>(
        lin_weight, linhi, linlo, EMB, EMB, EMBP);
    split_w_kernel<false><<<(IN_SIZE * EMBP + 255) / 256, 256>>>(
        wdec, wdechi, wdeclo, IN_SIZE, EMB, EMBP);

    // 1) h = sigmoid(x @ wenc^T + benc) -> bf16 hi/lo (padded stride EMBP)
    {
        dim3 grid((EMB + 127) / 128, mt);
        bgemm<true, true, true><<<grid, 256>>>(
            xhi, xlo, IN_SIZE, wenchi, wenclo, IN_SIZE, benc,
            nullptr, 0, hhi, hlo, EMBP, N_NODES, EMB, IN_SIZE);
    }
    // 2) h2 = h @ conv_weight (fp32)
    {
        dim3 grid((EMB + 127) / 128, mt);
        bgemm<false, false, false><<<grid, 256>>>(
            hhi, hlo, EMBP, convthi, convtlo, EMBP, nullptr,
            h2, EMB, nullptr, nullptr, 0, N_NODES, EMB, EMBP);
    }
    // 3) agg = h @ lin_weight^T (fp32, root term init)
    {
        dim3 grid((EMB + 127) / 128, mt);
        bgemm<false, false, false><<<grid, 256>>>(
            hhi, hlo, EMBP, linhi, linlo, EMBP, nullptr,
            agg, EMB, nullptr, nullptr, 0, N_NODES, EMB, EMBP);
    }
    // 4) agg += scatter(h2[src] * w -> dst)
    scatter_edges<<<N_EDGES, 128>>>(edge_index, edge_weight, h2, agg);
    // 5) split agg -> bf16 hi/lo
    {
        long long n = (long long)N_NODES * EMBP;
        split_agg_kernel<<<(unsigned)((n + 255) / 256), 256>>>(agg, agghi, agglo);
    }
    // 6) out = agg @ wdec^T + bdec (fp32)
    {
        dim3 grid((IN_SIZE + 127) / 128, mt);
        bgemm<false, true, false><<<grid, 256>>>(
            agghi, agglo, EMBP, wdechi, wdeclo, EMBP, bdec,
            out, IN_SIZE, nullptr, nullptr, 0, N_NODES, IN_SIZE, EMBP);
    }
}

// round 8
// speedup vs baseline: 2.0325x; 1.2076x over previous
#include <cuda_runtime.h>
#include <cuda_bf16.h>
#include <cstdint>

#define N_NODES 50000
#define N_EDGES 800000
#define IN_SIZE 1024
#define EMB 500
#define EMBP 512

// ---------------------------------------------------------------------------
// Scratch (device globals: allocation-free per harness rules)
// ---------------------------------------------------------------------------
__device__ __nv_bfloat16 g_xhi[(size_t)N_NODES * IN_SIZE];
__device__ __nv_bfloat16 g_xlo[(size_t)N_NODES * IN_SIZE];
__device__ __nv_bfloat16 g_hhi[(size_t)N_NODES * EMBP];
__device__ __nv_bfloat16 g_hlo[(size_t)N_NODES * EMBP];
__device__ float         g_h2[(size_t)N_NODES * EMBP];
__device__ float         g_agg[(size_t)N_NODES * EMBP];
__device__ __nv_bfloat16 g_agghi[(size_t)N_NODES * EMBP];
__device__ __nv_bfloat16 g_agglo[(size_t)N_NODES * EMBP];
// weight splits, padded [NP][Kp], K contiguous
__device__ __nv_bfloat16 g_wenchi[EMBP * IN_SIZE],  g_wenclo[EMBP * IN_SIZE];
__device__ __nv_bfloat16 g_convthi[EMBP * EMBP],    g_convtlo[EMBP * EMBP];
__device__ __nv_bfloat16 g_linhi[EMBP * EMBP],      g_linlo[EMBP * EMBP];
__device__ __nv_bfloat16 g_wdechi[IN_SIZE * EMBP],  g_wdeclo[IN_SIZE * EMBP];

__device__ __forceinline__ void split2(float f, __nv_bfloat16& hi, __nv_bfloat16& lo) {
    hi = __float2bfloat16_rn(f);
    lo = __float2bfloat16_rn(f - __bfloat162float(hi));
}

// ---------------------------------------------------------------------------
// Split kernels
// ---------------------------------------------------------------------------
__global__ __launch_bounds__(256) void split_x_kernel(
    const float4* __restrict__ x, __nv_bfloat16* __restrict__ hi,
    __nv_bfloat16* __restrict__ lo, long long n4)
{
    long long i = (long long)blockIdx.x * blockDim.x + threadIdx.x;
    if (i >= n4) return;
    float4 v = x[i];
    __nv_bfloat16 h0, h1, h2, h3, l0, l1, l2, l3;
    split2(v.x, h0, l0); split2(v.y, h1, l1);
    split2(v.z, h2, l2); split2(v.w, h3, l3);
    __nv_bfloat162* ph = reinterpret_cast<__nv_bfloat162*>(hi) + i * 2;
    __nv_bfloat162* pl = reinterpret_cast<__nv_bfloat162*>(lo) + i * 2;
    ph[0] = __nv_bfloat162(h0, h1); ph[1] = __nv_bfloat162(h2, h3);
    pl[0] = __nv_bfloat162(l0, l1); pl[1] = __nv_bfloat162(l2, l3);
}

// pad both N (rows) and K; TRANS reads src[k*N+n]
template <bool TRANS>
__global__ __launch_bounds__(256) void split_w_kernel(
    const float* __restrict__ src, __nv_bfloat16* __restrict__ hi,
    __nv_bfloat16* __restrict__ lo, int N, int K, int NP, int Kp)
{
    int idx = blockIdx.x * blockDim.x + threadIdx.x;
    if (idx >= NP * Kp) return;
    int n = idx / Kp, k = idx - n * Kp;
    float v = 0.f;
    if (n < N && k < K)
        v = TRANS ? src[(long long)k * N + n] : src[(long long)n * K + k];
    split2(v, hi[idx], lo[idx]);
}

// agg stride EMBP, pads already zero — straight split
__global__ __launch_bounds__(256) void split_agg_kernel(
    const float* __restrict__ agg, __nv_bfloat16* __restrict__ hi,
    __nv_bfloat16* __restrict__ lo)
{
    long long idx = (long long)blockIdx.x * blockDim.x + threadIdx.x;
    if (idx >= (long long)N_NODES * EMBP) return;
    split2(agg[idx], hi[idx], lo[idx]);
}

// ---------------------------------------------------------------------------
// bf16x3 split GEMM on mma.sync tensor cores, cp.async 3-stage pipeline.
// C[M,N] = act(A[M,K] @ B[N,K]^T + bias). BM=BN=128, BK=32, 256 threads.
// B padded to NP rows (grid.x = NP/128); K multiple of 32, pads zero.
// fp32 output path writes all padded columns (zeros beyond Nreal).
// ---------------------------------------------------------------------------
#define KPAD 40          // halves per smem row (80B stride, conflict-free ldmatrix)
#define HALF_STRIDE 5120 // 128 * KPAD halves per matrix-half
#define STG_HALVES 20480 // A(hi+lo) + B(hi+lo) per stage
#define NSTAGE 3
#define DYNSMEM (NSTAGE * STG_HALVES * 2)  // bytes = 122880

__device__ __forceinline__ void ldsm4(uint32_t (&r)[4], uint32_t addr) {
    asm volatile("ldmatrix.sync.aligned.m8n8.x4.shared.b16 {%0,%1,%2,%3}, [%4];"
                 : "=r"(r[0]), "=r"(r[1]), "=r"(r[2]), "=r"(r[3]) : "r"(addr));
}
__device__ __forceinline__ void mma_bf16(float (&c)[4], const uint32_t (&a)[4],
                                         uint32_t b0, uint32_t b1) {
    asm volatile(
        "mma.sync.aligned.m16n8k16.row.col.f32.bf16.bf16.f32 "
        "{%0,%1,%2,%3}, {%4,%5,%6,%7}, {%8,%9}, {%0,%1,%2,%3};"
        : "+f"(c[0]), "+f"(c[1]), "+f"(c[2]), "+f"(c[3])
        : "r"(a[0]), "r"(a[1]), "r"(a[2]), "r"(a[3]), "r"(b0), "r"(b1));
}
__device__ __forceinline__ void cpa16(uint32_t dst, const void* src, int sz) {
    asm volatile("cp.async.cg.shared.global [%0], [%1], 16, %2;"
                 :: "r"(dst), "l"(src), "r"(sz) : "memory");
}
__device__ __forceinline__ void cpa16u(uint32_t dst, const void* src) {
    asm volatile("cp.async.cg.shared.global [%0], [%1], 16;"
                 :: "r"(dst), "l"(src) : "memory");
}

template <bool PAIR, bool BIAS, bool SIG>
__global__ __launch_bounds__(256, 1) void bgemm(
    const __nv_bfloat16* __restrict__ Ahi, const __nv_bfloat16* __restrict__ Alo,
    int sA_, const __nv_bfloat16* __restrict__ Bhi,
    const __nv_bfloat16* __restrict__ Blo, int sB_,
    const float* __restrict__ bias,
    float* __restrict__ C, int sC,
    __nv_bfloat16* __restrict__ Chi, __nv_bfloat16* __restrict__ Clo, int sCp,
    int M, int Nreal, int K)
{
    extern __shared__ __nv_bfloat16 smem[];

    const int tid  = threadIdx.x;
    const int lane = tid & 31;
    const int warp = tid >> 5;
    const int wm = warp >> 1;   // 0..3
    const int wn = warp & 1;    // 0..1
    const int m0 = blockIdx.y * 128;
    const int n0 = blockIdx.x * 128;

    // cp.async mapping: thread -> (row, 2 chunks of 16B) for each matrix-half
    const int lrow = tid >> 1;
    const int cp0  = (tid & 1) * 2;   // chunk 0..3 within 64B row
    const int gmA  = m0 + lrow;
    const int szA  = (gmA < M) ? 16 : 0;
    const long long baseA = (long long)gmA * sA_ + cp0 * 8;
    const long long baseB = (long long)(n0 + lrow) * sB_ + cp0 * 8;
    const uint32_t drow = (uint32_t)(lrow * KPAD + cp0 * 8);

    float acc[2][8][4];
    #pragma unroll
    for (int i = 0; i < 2; i++)
        #pragma unroll
        for (int j = 0; j < 8; j++)
            #pragma unroll
            for (int e = 0; e < 4; e++) acc[i][j][e] = 0.f;

    const int g = lane >> 3, r8 = lane & 7;
    const int nk = K / 32;

    // ---- stage loader ----
    auto load_stage = [&](int st, int k0) {
        __nv_bfloat16* base = smem + st * STG_HALVES;
        uint32_t ah = (uint32_t)__cvta_generic_to_shared(base + drow);
        uint32_t al = ah + HALF_STRIDE * 2;         // bytes
        uint32_t bh = ah + 2 * HALF_STRIDE * 2;
        uint32_t bl = ah + 3 * HALF_STRIDE * 2;
        cpa16(ah,      Ahi + baseA + k0, szA);
        cpa16(ah + 16, Ahi + baseA + k0 + 8, szA);
        cpa16(al,      Alo + baseA + k0, szA);
        cpa16(al + 16, Alo + baseA + k0 + 8, szA);
        cpa16u(bh,      Bhi + baseB + k0);
        cpa16u(bh + 16, Bhi + baseB + k0 + 8);
        cpa16u(bl,      Blo + baseB + k0);
        cpa16u(bl + 16, Blo + baseB + k0 + 8);
    };

    // ---- prologue: stages 0,1 in flight ----
    load_stage(0, 0);
    asm volatile("cp.async.commit_group;" ::: "memory");
    if (nk > 1) load_stage(1, 32);
    asm volatile("cp.async.commit_group;" ::: "memory");

    for (int s = 0; s < nk; s++) {
        const int st = s % NSTAGE;
        if (s + 2 < nk) load_stage((s + 2) % NSTAGE, (s + 2) * 32);
        asm volatile("cp.async.commit_group;" ::: "memory");
        asm volatile("cp.async.wait_group 2;" ::: "memory");
        __syncthreads();

        __nv_bfloat16* bufA = smem + st * STG_HALVES;
        __nv_bfloat16* bufB = bufA + 2 * HALF_STRIDE;

        #pragma unroll
        for (int ks = 0; ks < 2; ks++) {
            const int kk = ks * 16;
            uint32_t a[2][2][4];
            #pragma unroll
            for (int h = 0; h < 2; h++)
                #pragma unroll
                for (int mt = 0; mt < 2; mt++) {
                    const int row = wm * 32 + mt * 16 + (g & 1) * 8 + r8;
                    const int col = kk + (g >> 1) * 8;
                    ldsm4(a[h][mt], (uint32_t)__cvta_generic_to_shared(
                              bufA + h * HALF_STRIDE + row * KPAD + col));
                }
            uint32_t b[2][4][4];
            #pragma unroll
            for (int h = 0; h < 2; h++)
                #pragma unroll
                for (int p = 0; p < 4; p++) {
                    const int row = wn * 64 + p * 16 + (g >> 1) * 8 + r8;
                    const int col = kk + (g & 1) * 8;
                    ldsm4(b[h][p], (uint32_t)__cvta_generic_to_shared(
                              bufB + h * HALF_STRIDE + row * KPAD + col));
                }
            #pragma unroll
            for (int mt = 0; mt < 2; mt++)
                #pragma unroll
                for (int p = 0; p < 4; p++)
                    #pragma unroll
                    for (int sx = 0; sx < 2; sx++) {
                        const int nt = p * 2 + sx;
                        const uint32_t bh0 = b[0][p][sx * 2], bh1 = b[0][p][sx * 2 + 1];
                        const uint32_t bl0 = b[1][p][sx * 2], bl1 = b[1][p][sx * 2 + 1];
                        mma_bf16(acc[mt][nt], a[0][mt], bh0, bh1);
                        mma_bf16(acc[mt][nt], a[0][mt], bl0, bl1);
                        mma_bf16(acc[mt][nt], a[1][mt], bh0, bh1);
                    }
        }
        __syncthreads();   // all reads done before this buffer is refilled
    }

    // ---- epilogue ----
    const int rq = lane >> 2, cq = (lane & 3) * 2;
    #pragma unroll
    for (int mt = 0; mt < 2; mt++)
        #pragma unroll
        for (int nt = 0; nt < 8; nt++) {
            const int gr0 = m0 + wm * 32 + mt * 16 + rq;
            const int gc0 = n0 + wn * 64 + nt * 8 + cq;
            #pragma unroll
            for (int e = 0; e < 4; e++) {
                const int gm = gr0 + (e >> 1) * 8;
                const int gn = gc0 + (e & 1);
                if (gm >= M) continue;
                float v = acc[mt][nt][e];
                if (gn < Nreal) {
                    if (BIAS) v += bias[gn];
                    if (SIG) v = 1.f / (1.f + expf(-v));
                } else {
                    v = 0.f;   // pad columns -> zero
                }
                if (PAIR) {
                    __nv_bfloat16 hi, lo;
                    split2(v, hi, lo);
                    const long long o = (long long)gm * sCp + gn;
                    Chi[o] = hi; Clo[o] = lo;
                } else {
                    C[(long long)gm * sC + gn] = v;  // padded stride, zeros in pads
                }
            }
        }
}

// ---------------------------------------------------------------------------
// Edge scatter: agg[dst] += h2[src] * w  (h2/agg stride EMBP)
// ---------------------------------------------------------------------------
__global__ __launch_bounds__(128) void scatter_edges(
    const int* __restrict__ edge_index, const float* __restrict__ ew,
    const float* __restrict__ h2, float* __restrict__ agg)
{
    const int e = blockIdx.x;
    const int src = edge_index[e];
    const int dst = edge_index[N_EDGES + e];
    const float w = ew[e];
    const int c = threadIdx.x * 4;
    if (c < EMB) {
        float4 v = *reinterpret_cast<const float4*>(&h2[(long long)src * EMBP + c]);
        v.x *= w; v.y *= w; v.z *= w; v.w *= w;
        float* p = &agg[(long long)dst * EMBP + c];
        asm volatile("red.global.add.v4.f32 [%0], {%1, %2, %3, %4};"
                     :: "l"(p), "f"(v.x), "f"(v.y), "f"(v.z), "f"(v.w)
                     : "memory");
    }
}

// ---------------------------------------------------------------------------
extern "C" void kernel_launch(void* const* d_in, const int* in_sizes, int n_in,
                              void* d_out, int out_size)
{
    const float* x           = (const float*)d_in[0];
    const int*   edge_index  = (const int*)  d_in[1];
    const float* edge_weight = (const float*)d_in[2];
    const float* wenc        = (const float*)d_in[3];  // [EMB, IN_SIZE]
    const float* benc        = (const float*)d_in[4];
    const float* wdec        = (const float*)d_in[5];  // [IN_SIZE, EMB]
    const float* bdec        = (const float*)d_in[6];
    const float* conv_weight = (const float*)d_in[7];  // [EMB, EMB] (k, n)
    const float* lin_weight  = (const float*)d_in[8];  // [EMB, EMB] (n, k)
    float* out = (float*)d_out;

    __nv_bfloat16 *xhi, *xlo, *hhi, *hlo, *agghi, *agglo;
    __nv_bfloat16 *wenchi, *wenclo, *convthi, *convtlo, *linhi, *linlo, *wdechi, *wdeclo;
    float *h2, *agg;
    cudaGetSymbolAddress((void**)&xhi, g_xhi);     cudaGetSymbolAddress((void**)&xlo, g_xlo);
    cudaGetSymbolAddress((void**)&hhi, g_hhi);     cudaGetSymbolAddress((void**)&hlo, g_hlo);
    cudaGetSymbolAddress((void**)&agghi, g_agghi); cudaGetSymbolAddress((void**)&agglo, g_agglo);
    cudaGetSymbolAddress((void**)&h2, g_h2);       cudaGetSymbolAddress((void**)&agg, g_agg);
    cudaGetSymbolAddress((void**)&wenchi, g_wenchi);   cudaGetSymbolAddress((void**)&wenclo, g_wenclo);
    cudaGetSymbolAddress((void**)&convthi, g_convthi); cudaGetSymbolAddress((void**)&convtlo, g_convtlo);
    cudaGetSymbolAddress((void**)&linhi, g_linhi);     cudaGetSymbolAddress((void**)&linlo, g_linlo);
    cudaGetSymbolAddress((void**)&wdechi, g_wdechi);   cudaGetSymbolAddress((void**)&wdeclo, g_wdeclo);

    cudaFuncSetAttribute(bgemm<true,  true,  true >, cudaFuncAttributeMaxDynamicSharedMemorySize, DYNSMEM);
    cudaFuncSetAttribute(bgemm<false, false, false>, cudaFuncAttributeMaxDynamicSharedMemorySize, DYNSMEM);
    cudaFuncSetAttribute(bgemm<false, true,  false>, cudaFuncAttributeMaxDynamicSharedMemorySize, DYNSMEM);

    const int mt = (N_NODES + 127) / 128;  // 391

    // ---- prep: splits (weights padded in N and K) ----
    {
        long long n4 = (long long)N_NODES * IN_SIZE / 4;
        split_x_kernel<<<(unsigned)((n4 + 255) / 256), 256>>>((const float4*)x, xhi, xlo, n4);
    }
    split_w_kernel<false><<<(EMBP * IN_SIZE + 255) / 256, 256>>>(
        wenc, wenchi, wenclo, EMB, IN_SIZE, EMBP, IN_SIZE);
    split_w_kernel<true><<<(EMBP * EMBP + 255) / 256, 256>>>(
        conv_weight, convthi, convtlo, EMB, EMB, EMBP, EMBP);
    split_w_kernel<false><<<(EMBP * EMBP + 255) / 256, 256>>>(
        lin_weight, linhi, linlo, EMB, EMB, EMBP, EMBP);
    split_w_kernel<false><<<(IN_SIZE * EMBP + 255) / 256, 256>>>(
        wdec, wdechi, wdeclo, IN_SIZE, EMB, IN_SIZE, EMBP);

    // 1) h = sigmoid(x @ wenc^T + benc) -> bf16 hi/lo pair (stride EMBP)
    {
        dim3 grid(EMBP / 128, mt);
        bgemm<true, true, true><<<grid, 256, DYNSMEM>>>(
            xhi, xlo, IN_SIZE, wenchi, wenclo, IN_SIZE, benc,
            nullptr, 0, hhi, hlo, EMBP, N_NODES, EMB, IN_SIZE);
    }
    // 2) h2 = h @ conv_weight (fp32, stride EMBP, pads zeroed by kernel)
    {
        dim3 grid(EMBP / 128, mt);
        bgemm<false, false, false><<<grid, 256, DYNSMEM>>>(
            hhi, hlo, EMBP, convthi, convtlo, EMBP, nullptr,
            h2, EMBP, nullptr, nullptr, 0, N_NODES, EMB, EMBP);
    }
    // 3) agg = h @ lin_weight^T (fp32 root term, pads zeroed)
    {
        dim3 grid(EMBP / 128, mt);
        bgemm<false, false, false><<<grid, 256, DYNSMEM>>>(
            hhi, hlo, EMBP, linhi, linlo, EMBP, nullptr,
            agg, EMBP, nullptr, nullptr, 0, N_NODES, EMB, EMBP);
    }
    // 4) agg += scatter(h2[src] * w -> dst)
    scatter_edges<<<N_EDGES, 128>>>(edge_index, edge_weight, h2, agg);
    // 5) split agg -> bf16 hi/lo
    {
        long long n = (long long)N_NODES * EMBP;
        split_agg_kernel<<<(unsigned)((n + 255) / 256), 256>>>(agg, agghi, agglo);
    }
    // 6) out = agg @ wdec^T + bdec (fp32)
    {
        dim3 grid(IN_SIZE / 128, mt);
        bgemm<false, true, false><<<grid, 256, DYNSMEM>>>(
            agghi, agglo, EMBP, wdechi, wdeclo, EMBP, bdec,
            out, IN_SIZE, nullptr, nullptr, 0, N_NODES, IN_SIZE, EMBP);
    }
}

// round 9
// speedup vs baseline: 2.2525x; 1.1082x over previous
#include <cuda_runtime.h>
#include <cuda_bf16.h>
#include <cstdint>

#define N_NODES 50000
#define N_EDGES 800000
#define IN_SIZE 1024
#define EMB 500
#define EMBP 512

// ---------------------------------------------------------------------------
// Scratch (device globals: allocation-free per harness rules)
// ---------------------------------------------------------------------------
__device__ __nv_bfloat16 g_xhi[(size_t)N_NODES * IN_SIZE];
__device__ __nv_bfloat16 g_xlo[(size_t)N_NODES * IN_SIZE];
__device__ __nv_bfloat16 g_hhi[(size_t)N_NODES * EMBP];
__device__ __nv_bfloat16 g_hlo[(size_t)N_NODES * EMBP];
__device__ float         g_h2[(size_t)N_NODES * EMBP];
__device__ float         g_agg[(size_t)N_NODES * EMBP];   // lin-term only
__device__ __nv_bfloat16 g_agghi[(size_t)N_NODES * EMBP];
__device__ __nv_bfloat16 g_agglo[(size_t)N_NODES * EMBP];
// weight splits, padded [NP][Kp], K contiguous
__device__ __nv_bfloat16 g_wenchi[EMBP * IN_SIZE],  g_wenclo[EMBP * IN_SIZE];
__device__ __nv_bfloat16 g_convthi[EMBP * EMBP],    g_convtlo[EMBP * EMBP];
__device__ __nv_bfloat16 g_linhi[EMBP * EMBP],      g_linlo[EMBP * EMBP];
__device__ __nv_bfloat16 g_wdechi[IN_SIZE * EMBP],  g_wdeclo[IN_SIZE * EMBP];
// CSR scratch
__device__ int   g_cnt[N_NODES + 1];   // counts -> row_ptr
__device__ int   g_cur[N_NODES];       // fill cursors
__device__ int   g_esrc[N_EDGES];      // src sorted by dst
__device__ float g_ewt[N_EDGES];       // weight sorted by dst

__device__ __forceinline__ void split2(float f, __nv_bfloat16& hi, __nv_bfloat16& lo) {
    hi = __float2bfloat16_rn(f);
    lo = __float2bfloat16_rn(f - __bfloat162float(hi));
}

// ---------------------------------------------------------------------------
// Split kernels
// ---------------------------------------------------------------------------
__global__ __launch_bounds__(256) void split_x_kernel(
    const float4* __restrict__ x, __nv_bfloat16* __restrict__ hi,
    __nv_bfloat16* __restrict__ lo, long long n4)
{
    long long i = (long long)blockIdx.x * blockDim.x + threadIdx.x;
    if (i >= n4) return;
    float4 v = x[i];
    __nv_bfloat16 h0, h1, h2, h3, l0, l1, l2, l3;
    split2(v.x, h0, l0); split2(v.y, h1, l1);
    split2(v.z, h2, l2); split2(v.w, h3, l3);
    __nv_bfloat162* ph = reinterpret_cast<__nv_bfloat162*>(hi) + i * 2;
    __nv_bfloat162* pl = reinterpret_cast<__nv_bfloat162*>(lo) + i * 2;
    ph[0] = __nv_bfloat162(h0, h1); ph[1] = __nv_bfloat162(h2, h3);
    pl[0] = __nv_bfloat162(l0, l1); pl[1] = __nv_bfloat162(l2, l3);
}

template <bool TRANS>
__global__ __launch_bounds__(256) void split_w_kernel(
    const float* __restrict__ src, __nv_bfloat16* __restrict__ hi,
    __nv_bfloat16* __restrict__ lo, int N, int K, int NP, int Kp)
{
    int idx = blockIdx.x * blockDim.x + threadIdx.x;
    if (idx >= NP * Kp) return;
    int n = idx / Kp, k = idx - n * Kp;
    float v = 0.f;
    if (n < N && k < K)
        v = TRANS ? src[(long long)k * N + n] : src[(long long)n * K + k];
    split2(v, hi[idx], lo[idx]);
}

// ---------------------------------------------------------------------------
// CSR build kernels
// ---------------------------------------------------------------------------
__global__ __launch_bounds__(256) void k_zero_cnt()
{
    int i = blockIdx.x * blockDim.x + threadIdx.x;
    if (i <= N_NODES) g_cnt[i] = 0;
}
__global__ __launch_bounds__(256) void k_count(const int* __restrict__ edge_index)
{
    int e = blockIdx.x * blockDim.x + threadIdx.x;
    if (e < N_EDGES) atomicAdd(&g_cnt[edge_index[N_EDGES + e]], 1);
}
#define SCAN_T 1024
#define SCAN_C 49   // 1024*49 = 50176 >= 50000
__global__ __launch_bounds__(SCAN_T) void k_scan()
{
    __shared__ int sh[SCAN_T];
    const int t = threadIdx.x;
    const int base = t * SCAN_C;
    int s = 0;
    #pragma unroll 4
    for (int j = 0; j < SCAN_C; j++) {
        int idx = base + j;
        if (idx < N_NODES) s += g_cnt[idx];
    }
    sh[t] = s;
    __syncthreads();
    for (int off = 1; off < SCAN_T; off <<= 1) {
        int v = (t >= off) ? sh[t - off] : 0;
        __syncthreads();
        sh[t] += v;
        __syncthreads();
    }
    int run = sh[t] - s;  // exclusive prefix
    for (int j = 0; j < SCAN_C; j++) {
        int idx = base + j;
        if (idx < N_NODES) {
            int c = g_cnt[idx];
            g_cnt[idx] = run;
            g_cur[idx] = run;
            run += c;
        }
    }
    if (t == 0) g_cnt[N_NODES] = N_EDGES;
}
__global__ __launch_bounds__(256) void k_fill(
    const int* __restrict__ edge_index, const float* __restrict__ ew)
{
    int e = blockIdx.x * blockDim.x + threadIdx.x;
    if (e >= N_EDGES) return;
    int dst = edge_index[N_EDGES + e];
    int pos = atomicAdd(&g_cur[dst], 1);
    g_esrc[pos] = edge_index[e];
    g_ewt[pos]  = ew[e];
}

// ---------------------------------------------------------------------------
// Gather (no atomics): per node, acc = agg_lin[n] + sum_e w_e * h2[src_e];
// writes bf16 hi/lo split directly (fuses split_agg).
// ---------------------------------------------------------------------------
__global__ __launch_bounds__(128) void gather_nodes(
    const float* __restrict__ h2, const float* __restrict__ agg,
    __nv_bfloat16* __restrict__ agghi, __nv_bfloat16* __restrict__ agglo)
{
    const int n = blockIdx.x;
    const int c = threadIdx.x * 4;   // 0..508
    const int beg = g_cnt[n], end = g_cnt[n + 1];
    float4 acc = *reinterpret_cast<const float4*>(&agg[(long long)n * EMBP + c]);
    #pragma unroll 2
    for (int e = beg; e < end; e++) {
        const int   s = g_esrc[e];
        const float w = g_ewt[e];
        float4 v = *reinterpret_cast<const float4*>(&h2[(long long)s * EMBP + c]);
        acc.x = fmaf(v.x, w, acc.x); acc.y = fmaf(v.y, w, acc.y);
        acc.z = fmaf(v.z, w, acc.z); acc.w = fmaf(v.w, w, acc.w);
    }
    __nv_bfloat16 h0, h1, h2b, h3, l0, l1, l2, l3;
    split2(acc.x, h0, l0); split2(acc.y, h1, l1);
    split2(acc.z, h2b, l2); split2(acc.w, h3, l3);
    const long long o = (long long)n * EMBP + c;
    *reinterpret_cast<__nv_bfloat162*>(agghi + o)     = __nv_bfloat162(h0, h1);
    *reinterpret_cast<__nv_bfloat162*>(agghi + o + 2) = __nv_bfloat162(h2b, h3);
    *reinterpret_cast<__nv_bfloat162*>(agglo + o)     = __nv_bfloat162(l0, l1);
    *reinterpret_cast<__nv_bfloat162*>(agglo + o + 2) = __nv_bfloat162(l2, l3);
}

// ---------------------------------------------------------------------------
// bf16x3 split GEMM, mma.sync + cp.async, SW128-swizzled smem, 3 stages,
// 2 CTAs/SM. BM=BN=128, BK=32, 256 threads. Row layout: [hi 64B | lo 64B].
// ---------------------------------------------------------------------------
#define STAGE_BYTES 32768          // A 16KB + B 16KB
#define NSTAGE 3
#define DYNSMEM (NSTAGE * STAGE_BYTES)   // 96 KB -> 2 CTAs/SM

__device__ __forceinline__ uint32_t sw128(uint32_t o) { return o ^ ((o >> 3) & 0x70); }

__device__ __forceinline__ void ldsm4(uint32_t (&r)[4], uint32_t addr) {
    asm volatile("ldmatrix.sync.aligned.m8n8.x4.shared.b16 {%0,%1,%2,%3}, [%4];"
                 : "=r"(r[0]), "=r"(r[1]), "=r"(r[2]), "=r"(r[3]) : "r"(addr));
}
__device__ __forceinline__ void mma_bf16(float (&c)[4], const uint32_t (&a)[4],
                                         uint32_t b0, uint32_t b1) {
    asm volatile(
        "mma.sync.aligned.m16n8k16.row.col.f32.bf16.bf16.f32 "
        "{%0,%1,%2,%3}, {%4,%5,%6,%7}, {%8,%9}, {%0,%1,%2,%3};"
        : "+f"(c[0]), "+f"(c[1]), "+f"(c[2]), "+f"(c[3])
        : "r"(a[0]), "r"(a[1]), "r"(a[2]), "r"(a[3]), "r"(b0), "r"(b1));
}
__device__ __forceinline__ void cpa16(uint32_t dst, const void* src, int sz) {
    asm volatile("cp.async.cg.shared.global [%0], [%1], 16, %2;"
                 :: "r"(dst), "l"(src), "r"(sz) : "memory");
}
__device__ __forceinline__ void cpa16u(uint32_t dst, const void* src) {
    asm volatile("cp.async.cg.shared.global [%0], [%1], 16;"
                 :: "r"(dst), "l"(src) : "memory");
}

template <bool PAIR, bool BIAS, bool SIG>
__global__ __launch_bounds__(256, 2) void bgemm(
    const __nv_bfloat16* __restrict__ Ahi, const __nv_bfloat16* __restrict__ Alo,
    int sA_, const __nv_bfloat16* __restrict__ Bhi,
    const __nv_bfloat16* __restrict__ Blo, int sB_,
    const float* __restrict__ bias,
    float* __restrict__ C, int sC,
    __nv_bfloat16* __restrict__ Chi, __nv_bfloat16* __restrict__ Clo, int sCp,
    int M, int Nreal, int K)
{
    extern __shared__ char smem[];

    const int tid  = threadIdx.x;
    const int lane = tid & 31;
    const int warp = tid >> 5;
    const int wm = warp >> 1;   // 0..3
    const int wn = warp & 1;    // 0..1
    const int m0 = blockIdx.y * 128;
    const int n0 = blockIdx.x * 128;

    // cp.async mapping: 2 threads/row; tid&1 selects hi(0)/lo(1) 64B half
    const int lrow = tid >> 1;
    const int half = tid & 1;
    const int gmA  = m0 + lrow;
    const int szA  = (gmA < M) ? 16 : 0;
    const __nv_bfloat16* srcA = (half ? Alo : Ahi) + (long long)gmA * sA_;
    const __nv_bfloat16* srcB = (half ? Blo : Bhi) + (long long)(n0 + lrow) * sB_;
    const uint32_t smem_u = (uint32_t)__cvta_generic_to_shared(smem);
    // 4 swizzled dst offsets (16B chunks) within the row
    uint32_t dOff[4];
    #pragma unroll
    for (int cb = 0; cb < 4; cb++)
        dOff[cb] = sw128((uint32_t)(lrow * 128 + half * 64 + cb * 16));

    float acc[2][8][4];
    #pragma unroll
    for (int i = 0; i < 2; i++)
        #pragma unroll
        for (int j = 0; j < 8; j++)
            #pragma unroll
            for (int e = 0; e < 4; e++) acc[i][j][e] = 0.f;

    const int g = lane >> 3, r8 = lane & 7;
    const int nk = K / 32;

    auto load_stage = [&](int st, int k0) {
        const uint32_t aBase = smem_u + st * STAGE_BYTES;
        const uint32_t bBase = aBase + 16384;
        #pragma unroll
        for (int cb = 0; cb < 4; cb++)
            cpa16(aBase + dOff[cb], srcA + k0 + cb * 8, szA);
        #pragma unroll
        for (int cb = 0; cb < 4; cb++)
            cpa16u(bBase + dOff[cb], srcB + k0 + cb * 8);
        asm volatile("cp.async.commit_group;" ::: "memory");
    };

    // prologue: 2 stages in flight
    load_stage(0, 0);
    load_stage(1, 32);

    // precomputed ldsm offsets (pre-swizzle row/col)
    const int aRowBase = wm * 32 + (g & 1) * 8 + r8;
    const int aColB    = (g >> 1) * 16;            // bytes within 64B half
    const int bRowBase = wn * 64 + (g >> 1) * 8 + r8;
    const int bColB    = (g & 1) * 16;

    for (int s = 0; s < nk; s++) {
        if (s + 1 < nk) { asm volatile("cp.async.wait_group 1;" ::: "memory"); }
        else            { asm volatile("cp.async.wait_group 0;" ::: "memory"); }
        __syncthreads();   // stage s visible; everyone done computing s-1
        if (s + 2 < nk) load_stage((s + 2) % NSTAGE, (s + 2) * 32);

        const uint32_t aBuf = smem_u + (s % NSTAGE) * STAGE_BYTES;
        const uint32_t bBuf = aBuf + 16384;

        #pragma unroll
        for (int ks = 0; ks < 2; ks++) {
            const int kkB = ks * 32;   // bytes: 16 halves
            uint32_t a[2][2][4];
            #pragma unroll
            for (int h = 0; h < 2; h++)
                #pragma unroll
                for (int mt = 0; mt < 2; mt++) {
                    const uint32_t off = (uint32_t)((aRowBase + mt * 16) * 128
                                                    + h * 64 + kkB + aColB);
                    ldsm4(a[h][mt], aBuf + sw128(off));
                }
            #pragma unroll
            for (int p = 0; p < 4; p++) {
                uint32_t bh[4], bl[4];
                {
                    const uint32_t off = (uint32_t)((bRowBase + p * 16) * 128
                                                    + kkB + bColB);
                    ldsm4(bh, bBuf + sw128(off));
                    ldsm4(bl, bBuf + sw128(off + 64));
                }
                #pragma unroll
                for (int sx = 0; sx < 2; sx++) {
                    const int nt = p * 2 + sx;
                    #pragma unroll
                    for (int mt = 0; mt < 2; mt++) {
                        mma_bf16(acc[mt][nt], a[0][mt], bh[sx * 2], bh[sx * 2 + 1]);
                        mma_bf16(acc[mt][nt], a[0][mt], bl[sx * 2], bl[sx * 2 + 1]);
                        mma_bf16(acc[mt][nt], a[1][mt], bh[sx * 2], bh[sx * 2 + 1]);
                    }
                }
            }
        }
    }

    // ---- epilogue ----
    const int rq = lane >> 2, cq = (lane & 3) * 2;
    #pragma unroll
    for (int mt = 0; mt < 2; mt++)
        #pragma unroll
        for (int nt = 0; nt < 8; nt++) {
            const int gr0 = m0 + wm * 32 + mt * 16 + rq;
            const int gc0 = n0 + wn * 64 + nt * 8 + cq;
            #pragma unroll
            for (int e = 0; e < 4; e++) {
                const int gm = gr0 + (e >> 1) * 8;
                const int gn = gc0 + (e & 1);
                if (gm >= M) continue;
                float v = acc[mt][nt][e];
                if (gn < Nreal) {
                    if (BIAS) v += bias[gn];
                    if (SIG) v = 1.f / (1.f + expf(-v));
                } else {
                    v = 0.f;   // pad columns -> zero
                }
                if (PAIR) {
                    __nv_bfloat16 hi, lo;
                    split2(v, hi, lo);
                    const long long o = (long long)gm * sCp + gn;
                    Chi[o] = hi; Clo[o] = lo;
                } else {
                    C[(long long)gm * sC + gn] = v;
                }
            }
        }
}

// ---------------------------------------------------------------------------
extern "C" void kernel_launch(void* const* d_in, const int* in_sizes, int n_in,
                              void* d_out, int out_size)
{
    const float* x           = (const float*)d_in[0];
    const int*   edge_index  = (const int*)  d_in[1];
    const float* edge_weight = (const float*)d_in[2];
    const float* wenc        = (const float*)d_in[3];  // [EMB, IN_SIZE]
    const float* benc        = (const float*)d_in[4];
    const float* wdec        = (const float*)d_in[5];  // [IN_SIZE, EMB]
    const float* bdec        = (const float*)d_in[6];
    const float* conv_weight = (const float*)d_in[7];  // [EMB, EMB] (k, n)
    const float* lin_weight  = (const float*)d_in[8];  // [EMB, EMB] (n, k)
    float* out = (float*)d_out;

    __nv_bfloat16 *xhi, *xlo, *hhi, *hlo, *agghi, *agglo;
    __nv_bfloat16 *wenchi, *wenclo, *convthi, *convtlo, *linhi, *linlo, *wdechi, *wdeclo;
    float *h2, *agg;
    cudaGetSymbolAddress((void**)&xhi, g_xhi);     cudaGetSymbolAddress((void**)&xlo, g_xlo);
    cudaGetSymbolAddress((void**)&hhi, g_hhi);     cudaGetSymbolAddress((void**)&hlo, g_hlo);
    cudaGetSymbolAddress((void**)&agghi, g_agghi); cudaGetSymbolAddress((void**)&agglo, g_agglo);
    cudaGetSymbolAddress((void**)&h2, g_h2);       cudaGetSymbolAddress((void**)&agg, g_agg);
    cudaGetSymbolAddress((void**)&wenchi, g_wenchi);   cudaGetSymbolAddress((void**)&wenclo, g_wenclo);
    cudaGetSymbolAddress((void**)&convthi, g_convthi); cudaGetSymbolAddress((void**)&convtlo, g_convtlo);
    cudaGetSymbolAddress((void**)&linhi, g_linhi);     cudaGetSymbolAddress((void**)&linlo, g_linlo);
    cudaGetSymbolAddress((void**)&wdechi, g_wdechi);   cudaGetSymbolAddress((void**)&wdeclo, g_wdeclo);

    cudaFuncSetAttribute(bgemm<true,  true,  true >, cudaFuncAttributeMaxDynamicSharedMemorySize, DYNSMEM);
    cudaFuncSetAttribute(bgemm<false, false, false>, cudaFuncAttributeMaxDynamicSharedMemorySize, DYNSMEM);
    cudaFuncSetAttribute(bgemm<false, true,  false>, cudaFuncAttributeMaxDynamicSharedMemorySize, DYNSMEM);

    const int mt = (N_NODES + 127) / 128;  // 391

    // ---- prep: splits + CSR build (independent of GEMM chain) ----
    {
        long long n4 = (long long)N_NODES * IN_SIZE / 4;
        split_x_kernel<<<(unsigned)((n4 + 255) / 256), 256>>>((const float4*)x, xhi, xlo, n4);
    }
    split_w_kernel<false><<<(EMBP * IN_SIZE + 255) / 256, 256>>>(
        wenc, wenchi, wenclo, EMB, IN_SIZE, EMBP, IN_SIZE);
    split_w_kernel<true><<<(EMBP * EMBP + 255) / 256, 256>>>(
        conv_weight, convthi, convtlo, EMB, EMB, EMBP, EMBP);
    split_w_kernel<false><<<(EMBP * EMBP + 255) / 256, 256>>>(
        lin_weight, linhi, linlo, EMB, EMB, EMBP, EMBP);
    split_w_kernel<false><<<(IN_SIZE * EMBP + 255) / 256, 256>>>(
        wdec, wdechi, wdeclo, IN_SIZE, EMB, IN_SIZE, EMBP);

    k_zero_cnt<<<(N_NODES + 1 + 255) / 256, 256>>>();
    k_count<<<(N_EDGES + 255) / 256, 256>>>(edge_index);
    k_scan<<<1, SCAN_T>>>();
    k_fill<<<(N_EDGES + 255) / 256, 256>>>(edge_index, edge_weight);

    // 1) h = sigmoid(x @ wenc^T + benc) -> bf16 hi/lo pair
    {
        dim3 grid(EMBP / 128, mt);
        bgemm<true, true, true><<<grid, 256, DYNSMEM>>>(
            xhi, xlo, IN_SIZE, wenchi, wenclo, IN_SIZE, benc,
            nullptr, 0, hhi, hlo, EMBP, N_NODES, EMB, IN_SIZE);
    }
    // 2) h2 = h @ conv_weight (fp32, stride EMBP, pads zero)
    {
        dim3 grid(EMBP / 128, mt);
        bgemm<false, false, false><<<grid, 256, DYNSMEM>>>(
            hhi, hlo, EMBP, convthi, convtlo, EMBP, nullptr,
            h2, EMBP, nullptr, nullptr, 0, N_NODES, EMB, EMBP);
    }
    // 3) agg = h @ lin_weight^T (fp32 lin term, pads zero)
    {
        dim3 grid(EMBP / 128, mt);
        bgemm<false, false, false><<<grid, 256, DYNSMEM>>>(
            hhi, hlo, EMBP, linhi, linlo, EMBP, nullptr,
            agg, EMBP, nullptr, nullptr, 0, N_NODES, EMB, EMBP);
    }
    // 4) gather (CSR, no atomics) + fused bf16 split of final agg
    gather_nodes<<<N_NODES, 128>>>(h2, agg, agghi, agglo);
    // 5) out = agg @ wdec^T + bdec (fp32)
    {
        dim3 grid(IN_SIZE / 128, mt);
        bgemm<false, true, false><<<grid, 256, DYNSMEM>>>(
            agghi, agglo, EMBP, wdechi, wdeclo, EMBP, bdec,
            out, IN_SIZE, nullptr, nullptr, 0, N_NODES, IN_SIZE, EMBP);
    }
}

// round 10
// speedup vs baseline: 2.2745x; 1.0098x over previous
#include <cuda_runtime.h>
#include <cuda_bf16.h>
#include <cuda_fp16.h>
#include <cstdint>

#define N_NODES 50000
#define N_EDGES 800000
#define IN_SIZE 1024
#define EMB 500
#define EMBP 512

// ---------------------------------------------------------------------------
// Scratch (device globals: allocation-free per harness rules)
// ---------------------------------------------------------------------------
__device__ __nv_bfloat16 g_xhi[(size_t)N_NODES * IN_SIZE];
__device__ __nv_bfloat16 g_xlo[(size_t)N_NODES * IN_SIZE];
__device__ __nv_bfloat16 g_hhi[(size_t)N_NODES * EMBP];
__device__ __nv_bfloat16 g_hlo[(size_t)N_NODES * EMBP];
__device__ __half        g_h2h[(size_t)N_NODES * EMBP];   // conv output, fp16
__device__ float         g_agg[(size_t)N_NODES * EMBP];   // lin-term only
__device__ __nv_bfloat16 g_agghi[(size_t)N_NODES * EMBP];
__device__ __nv_bfloat16 g_agglo[(size_t)N_NODES * EMBP];
// weight splits, padded [NP][Kp], K contiguous
__device__ __nv_bfloat16 g_wenchi[EMBP * IN_SIZE],  g_wenclo[EMBP * IN_SIZE];
__device__ __nv_bfloat16 g_convthi[EMBP * EMBP],    g_convtlo[EMBP * EMBP];
__device__ __nv_bfloat16 g_linhi[EMBP * EMBP],      g_linlo[EMBP * EMBP];
__device__ __nv_bfloat16 g_wdechi[IN_SIZE * EMBP],  g_wdeclo[IN_SIZE * EMBP];
// CSR scratch
__device__ int   g_cnt[N_NODES + 1];   // counts -> row_ptr
__device__ int   g_cur[N_NODES];       // fill cursors
__device__ int   g_esrc[N_EDGES];      // src sorted by dst
__device__ float g_ewt[N_EDGES];       // weight sorted by dst

__device__ __forceinline__ void split2(float f, __nv_bfloat16& hi, __nv_bfloat16& lo) {
    hi = __float2bfloat16_rn(f);
    lo = __float2bfloat16_rn(f - __bfloat162float(hi));
}

// ---------------------------------------------------------------------------
// Split kernels
// ---------------------------------------------------------------------------
__global__ __launch_bounds__(256) void split_x_kernel(
    const float4* __restrict__ x, __nv_bfloat16* __restrict__ hi,
    __nv_bfloat16* __restrict__ lo, long long n4)
{
    long long i = (long long)blockIdx.x * blockDim.x + threadIdx.x;
    if (i >= n4) return;
    float4 v = x[i];
    __nv_bfloat16 h0, h1, h2, h3, l0, l1, l2, l3;
    split2(v.x, h0, l0); split2(v.y, h1, l1);
    split2(v.z, h2, l2); split2(v.w, h3, l3);
    __nv_bfloat162* ph = reinterpret_cast<__nv_bfloat162*>(hi) + i * 2;
    __nv_bfloat162* pl = reinterpret_cast<__nv_bfloat162*>(lo) + i * 2;
    ph[0] = __nv_bfloat162(h0, h1); ph[1] = __nv_bfloat162(h2, h3);
    pl[0] = __nv_bfloat162(l0, l1); pl[1] = __nv_bfloat162(l2, l3);
}

template <bool TRANS>
__global__ __launch_bounds__(256) void split_w_kernel(
    const float* __restrict__ src, __nv_bfloat16* __restrict__ hi,
    __nv_bfloat16* __restrict__ lo, int N, int K, int NP, int Kp)
{
    int idx = blockIdx.x * blockDim.x + threadIdx.x;
    if (idx >= NP * Kp) return;
    int n = idx / Kp, k = idx - n * Kp;
    float v = 0.f;
    if (n < N && k < K)
        v = TRANS ? src[(long long)k * N + n] : src[(long long)n * K + k];
    split2(v, hi[idx], lo[idx]);
}

// ---------------------------------------------------------------------------
// CSR build kernels
// ---------------------------------------------------------------------------
__global__ __launch_bounds__(256) void k_zero_cnt()
{
    int i = blockIdx.x * blockDim.x + threadIdx.x;
    if (i <= N_NODES) g_cnt[i] = 0;
}
__global__ __launch_bounds__(256) void k_count(const int* __restrict__ edge_index)
{
    int e = blockIdx.x * blockDim.x + threadIdx.x;
    if (e < N_EDGES) atomicAdd(&g_cnt[edge_index[N_EDGES + e]], 1);
}
#define SCAN_T 1024
#define SCAN_C 49   // 1024*49 = 50176 >= 50000
__global__ __launch_bounds__(SCAN_T) void k_scan()
{
    __shared__ int sh[SCAN_T];
    const int t = threadIdx.x;
    const int base = t * SCAN_C;
    int s = 0;
    #pragma unroll 4
    for (int j = 0; j < SCAN_C; j++) {
        int idx = base + j;
        if (idx < N_NODES) s += g_cnt[idx];
    }
    sh[t] = s;
    __syncthreads();
    for (int off = 1; off < SCAN_T; off <<= 1) {
        int v = (t >= off) ? sh[t - off] : 0;
        __syncthreads();
        sh[t] += v;
        __syncthreads();
    }
    int run = sh[t] - s;  // exclusive prefix
    for (int j = 0; j < SCAN_C; j++) {
        int idx = base + j;
        if (idx < N_NODES) {
            int c = g_cnt[idx];
            g_cnt[idx] = run;
            g_cur[idx] = run;
            run += c;
        }
    }
    if (t == 0) g_cnt[N_NODES] = N_EDGES;
}
__global__ __launch_bounds__(256) void k_fill(
    const int* __restrict__ edge_index, const float* __restrict__ ew)
{
    int e = blockIdx.x * blockDim.x + threadIdx.x;
    if (e >= N_EDGES) return;
    int dst = edge_index[N_EDGES + e];
    int pos = atomicAdd(&g_cur[dst], 1);
    g_esrc[pos] = edge_index[e];
    g_ewt[pos]  = ew[e];
}

// ---------------------------------------------------------------------------
// Gather (no atomics): per node, acc = agg_lin[n] + sum_e w_e * h2[src_e];
// h2 read as fp16 (half traffic), fp32 accumulate; writes bf16 hi/lo split.
// ---------------------------------------------------------------------------
__global__ __launch_bounds__(128) void gather_nodes(
    const __half* __restrict__ h2h, const float* __restrict__ agg,
    __nv_bfloat16* __restrict__ agghi, __nv_bfloat16* __restrict__ agglo)
{
    const int n = blockIdx.x;
    const int c = threadIdx.x * 4;   // 0..508
    const int beg = g_cnt[n], end = g_cnt[n + 1];
    float4 acc = *reinterpret_cast<const float4*>(&agg[(long long)n * EMBP + c]);

    int e = beg;
    for (; e + 1 < end; e += 2) {
        const int   s0 = g_esrc[e],     s1 = g_esrc[e + 1];
        const float w0 = g_ewt[e],      w1 = g_ewt[e + 1];
        const __half2* p0 = reinterpret_cast<const __half2*>(h2h + (long long)s0 * EMBP + c);
        const __half2* p1 = reinterpret_cast<const __half2*>(h2h + (long long)s1 * EMBP + c);
        const __half2 a0 = p0[0], a1 = p0[1];
        const __half2 b0 = p1[0], b1 = p1[1];
        float2 f0 = __half22float2(a0), f1 = __half22float2(a1);
        float2 f2 = __half22float2(b0), f3 = __half22float2(b1);
        acc.x = fmaf(f0.x, w0, acc.x); acc.y = fmaf(f0.y, w0, acc.y);
        acc.z = fmaf(f1.x, w0, acc.z); acc.w = fmaf(f1.y, w0, acc.w);
        acc.x = fmaf(f2.x, w1, acc.x); acc.y = fmaf(f2.y, w1, acc.y);
        acc.z = fmaf(f3.x, w1, acc.z); acc.w = fmaf(f3.y, w1, acc.w);
    }
    if (e < end) {
        const int   s0 = g_esrc[e];
        const float w0 = g_ewt[e];
        const __half2* p0 = reinterpret_cast<const __half2*>(h2h + (long long)s0 * EMBP + c);
        float2 f0 = __half22float2(p0[0]), f1 = __half22float2(p0[1]);
        acc.x = fmaf(f0.x, w0, acc.x); acc.y = fmaf(f0.y, w0, acc.y);
        acc.z = fmaf(f1.x, w0, acc.z); acc.w = fmaf(f1.y, w0, acc.w);
    }

    __nv_bfloat16 h0, h1, h2b, h3, l0, l1, l2, l3;
    split2(acc.x, h0, l0); split2(acc.y, h1, l1);
    split2(acc.z, h2b, l2); split2(acc.w, h3, l3);
    const long long o = (long long)n * EMBP + c;
    *reinterpret_cast<__nv_bfloat162*>(agghi + o)     = __nv_bfloat162(h0, h1);
    *reinterpret_cast<__nv_bfloat162*>(agghi + o + 2) = __nv_bfloat162(h2b, h3);
    *reinterpret_cast<__nv_bfloat162*>(agglo + o)     = __nv_bfloat162(l0, l1);
    *reinterpret_cast<__nv_bfloat162*>(agglo + o + 2) = __nv_bfloat162(l2, l3);
}

// ---------------------------------------------------------------------------
// bf16x3 split GEMM, mma.sync + cp.async, SW128-swizzled smem, 3 stages,
// 2 CTAs/SM. BM=BN=128, BK=32, 256 threads. Row layout: [hi 64B | lo 64B].
// OMODE: 0 = fp32 out, 1 = bf16 hi/lo pair out, 2 = fp16 out.
// mma order is term-major per p-group to break accumulator RAW chains.
// ---------------------------------------------------------------------------
#define STAGE_BYTES 32768          // A 16KB + B 16KB
#define NSTAGE 3
#define DYNSMEM (NSTAGE * STAGE_BYTES)   // 96 KB -> 2 CTAs/SM

__device__ __forceinline__ uint32_t sw128(uint32_t o) { return o ^ ((o >> 3) & 0x70); }

__device__ __forceinline__ void ldsm4(uint32_t (&r)[4], uint32_t addr) {
    asm volatile("ldmatrix.sync.aligned.m8n8.x4.shared.b16 {%0,%1,%2,%3}, [%4];"
                 : "=r"(r[0]), "=r"(r[1]), "=r"(r[2]), "=r"(r[3]) : "r"(addr));
}
__device__ __forceinline__ void mma_bf16(float (&c)[4], const uint32_t (&a)[4],
                                         uint32_t b0, uint32_t b1) {
    asm volatile(
        "mma.sync.aligned.m16n8k16.row.col.f32.bf16.bf16.f32 "
        "{%0,%1,%2,%3}, {%4,%5,%6,%7}, {%8,%9}, {%0,%1,%2,%3};"
        : "+f"(c[0]), "+f"(c[1]), "+f"(c[2]), "+f"(c[3])
        : "r"(a[0]), "r"(a[1]), "r"(a[2]), "r"(a[3]), "r"(b0), "r"(b1));
}
__device__ __forceinline__ void cpa16(uint32_t dst, const void* src, int sz) {
    asm volatile("cp.async.cg.shared.global [%0], [%1], 16, %2;"
                 :: "r"(dst), "l"(src), "r"(sz) : "memory");
}
__device__ __forceinline__ void cpa16u(uint32_t dst, const void* src) {
    asm volatile("cp.async.cg.shared.global [%0], [%1], 16;"
                 :: "r"(dst), "l"(src) : "memory");
}

template <int OMODE, bool BIAS, bool SIG>
__global__ __launch_bounds__(256, 2) void bgemm(
    const __nv_bfloat16* __restrict__ Ahi, const __nv_bfloat16* __restrict__ Alo,
    int sA_, const __nv_bfloat16* __restrict__ Bhi,
    const __nv_bfloat16* __restrict__ Blo, int sB_,
    const float* __restrict__ bias,
    float* __restrict__ C, __half* __restrict__ Ch, int sC,
    __nv_bfloat16* __restrict__ Chi, __nv_bfloat16* __restrict__ Clo, int sCp,
    int M, int Nreal, int K)
{
    extern __shared__ char smem[];

    const int tid  = threadIdx.x;
    const int lane = tid & 31;
    const int warp = tid >> 5;
    const int wm = warp >> 1;   // 0..3
    const int wn = warp & 1;    // 0..1
    const int m0 = blockIdx.y * 128;
    const int n0 = blockIdx.x * 128;

    // cp.async mapping: 2 threads/row; tid&1 selects hi(0)/lo(1) 64B half
    const int lrow = tid >> 1;
    const int half = tid & 1;
    const int gmA  = m0 + lrow;
    const int szA  = (gmA < M) ? 16 : 0;
    const __nv_bfloat16* srcA = (half ? Alo : Ahi) + (long long)gmA * sA_;
    const __nv_bfloat16* srcB = (half ? Blo : Bhi) + (long long)(n0 + lrow) * sB_;
    const uint32_t smem_u = (uint32_t)__cvta_generic_to_shared(smem);
    uint32_t dOff[4];
    #pragma unroll
    for (int cb = 0; cb < 4; cb++)
        dOff[cb] = sw128((uint32_t)(lrow * 128 + half * 64 + cb * 16));

    float acc[2][8][4];
    #pragma unroll
    for (int i = 0; i < 2; i++)
        #pragma unroll
        for (int j = 0; j < 8; j++)
            #pragma unroll
            for (int e = 0; e < 4; e++) acc[i][j][e] = 0.f;

    const int g = lane >> 3, r8 = lane & 7;
    const int nk = K / 32;

    auto load_stage = [&](int st, int k0) {
        const uint32_t aBase = smem_u + st * STAGE_BYTES;
        const uint32_t bBase = aBase + 16384;
        #pragma unroll
        for (int cb = 0; cb < 4; cb++)
            cpa16(aBase + dOff[cb], srcA + k0 + cb * 8, szA);
        #pragma unroll
        for (int cb = 0; cb < 4; cb++)
            cpa16u(bBase + dOff[cb], srcB + k0 + cb * 8);
        asm volatile("cp.async.commit_group;" ::: "memory");
    };

    load_stage(0, 0);
    load_stage(1, 32);

    const int aRowBase = wm * 32 + (g & 1) * 8 + r8;
    const int aColB    = (g >> 1) * 16;
    const int bRowBase = wn * 64 + (g >> 1) * 8 + r8;
    const int bColB    = (g & 1) * 16;

    for (int s = 0; s < nk; s++) {
        if (s + 1 < nk) { asm volatile("cp.async.wait_group 1;" ::: "memory"); }
        else            { asm volatile("cp.async.wait_group 0;" ::: "memory"); }
        __syncthreads();
        if (s + 2 < nk) load_stage((s + 2) % NSTAGE, (s + 2) * 32);

        const uint32_t aBuf = smem_u + (s % NSTAGE) * STAGE_BYTES;
        const uint32_t bBuf = aBuf + 16384;

        #pragma unroll
        for (int ks = 0; ks < 2; ks++) {
            const int kkB = ks * 32;
            uint32_t a[2][2][4];
            #pragma unroll
            for (int h = 0; h < 2; h++)
                #pragma unroll
                for (int mt = 0; mt < 2; mt++) {
                    const uint32_t off = (uint32_t)((aRowBase + mt * 16) * 128
                                                    + h * 64 + kkB + aColB);
                    ldsm4(a[h][mt], aBuf + sw128(off));
                }
            #pragma unroll
            for (int p = 0; p < 4; p++) {
                uint32_t bh[4], bl[4];
                {
                    const uint32_t off = (uint32_t)((bRowBase + p * 16) * 128
                                                    + kkB + bColB);
                    ldsm4(bh, bBuf + sw128(off));
                    ldsm4(bl, bBuf + sw128(off + 64));
                }
                // term-major: 4 independent accs per term, then reuse 4 apart
                #pragma unroll
                for (int sx = 0; sx < 2; sx++)
                    #pragma unroll
                    for (int mt = 0; mt < 2; mt++)
                        mma_bf16(acc[mt][p * 2 + sx], a[0][mt],
                                 bh[sx * 2], bh[sx * 2 + 1]);
                #pragma unroll
                for (int sx = 0; sx < 2; sx++)
                    #pragma unroll
                    for (int mt = 0; mt < 2; mt++)
                        mma_bf16(acc[mt][p * 2 + sx], a[0][mt],
                                 bl[sx * 2], bl[sx * 2 + 1]);
                #pragma unroll
                for (int sx = 0; sx < 2; sx++)
                    #pragma unroll
                    for (int mt = 0; mt < 2; mt++)
                        mma_bf16(acc[mt][p * 2 + sx], a[1][mt],
                                 bh[sx * 2], bh[sx * 2 + 1]);
            }
        }
    }

    // ---- epilogue ----
    const int rq = lane >> 2, cq = (lane & 3) * 2;
    #pragma unroll
    for (int mt = 0; mt < 2; mt++)
        #pragma unroll
        for (int nt = 0; nt < 8; nt++) {
            const int gr0 = m0 + wm * 32 + mt * 16 + rq;
            const int gc0 = n0 + wn * 64 + nt * 8 + cq;
            #pragma unroll
            for (int e = 0; e < 4; e++) {
                const int gm = gr0 + (e >> 1) * 8;
                const int gn = gc0 + (e & 1);
                if (gm >= M) continue;
                float v = acc[mt][nt][e];
                if (gn < Nreal) {
                    if (BIAS) v += bias[gn];
                    if (SIG) v = 1.f / (1.f + expf(-v));
                } else {
                    v = 0.f;   // pad columns -> zero
                }
                if (OMODE == 1) {
                    __nv_bfloat16 hi, lo;
                    split2(v, hi, lo);
                    const long long o = (long long)gm * sCp + gn;
                    Chi[o] = hi; Clo[o] = lo;
                } else if (OMODE == 2) {
                    Ch[(long long)gm * sC + gn] = __float2half_rn(v);
                } else {
                    C[(long long)gm * sC + gn] = v;
                }
            }
        }
}

// ---------------------------------------------------------------------------
extern "C" void kernel_launch(void* const* d_in, const int* in_sizes, int n_in,
                              void* d_out, int out_size)
{
    const float* x           = (const float*)d_in[0];
    const int*   edge_index  = (const int*)  d_in[1];
    const float* edge_weight = (const float*)d_in[2];
    const float* wenc        = (const float*)d_in[3];  // [EMB, IN_SIZE]
    const float* benc        = (const float*)d_in[4];
    const float* wdec        = (const float*)d_in[5];  // [IN_SIZE, EMB]
    const float* bdec        = (const float*)d_in[6];
    const float* conv_weight = (const float*)d_in[7];  // [EMB, EMB] (k, n)
    const float* lin_weight  = (const float*)d_in[8];  // [EMB, EMB] (n, k)
    float* out = (float*)d_out;

    __nv_bfloat16 *xhi, *xlo, *hhi, *hlo, *agghi, *agglo;
    __nv_bfloat16 *wenchi, *wenclo, *convthi, *convtlo, *linhi, *linlo, *wdechi, *wdeclo;
    __half *h2h;
    float *agg;
    cudaGetSymbolAddress((void**)&xhi, g_xhi);     cudaGetSymbolAddress((void**)&xlo, g_xlo);
    cudaGetSymbolAddress((void**)&hhi, g_hhi);     cudaGetSymbolAddress((void**)&hlo, g_hlo);
    cudaGetSymbolAddress((void**)&agghi, g_agghi); cudaGetSymbolAddress((void**)&agglo, g_agglo);
    cudaGetSymbolAddress((void**)&h2h, g_h2h);     cudaGetSymbolAddress((void**)&agg, g_agg);
    cudaGetSymbolAddress((void**)&wenchi, g_wenchi);   cudaGetSymbolAddress((void**)&wenclo, g_wenclo);
    cudaGetSymbolAddress((void**)&convthi, g_convthi); cudaGetSymbolAddress((void**)&convtlo, g_convtlo);
    cudaGetSymbolAddress((void**)&linhi, g_linhi);     cudaGetSymbolAddress((void**)&linlo, g_linlo);
    cudaGetSymbolAddress((void**)&wdechi, g_wdechi);   cudaGetSymbolAddress((void**)&wdeclo, g_wdeclo);

    cudaFuncSetAttribute(bgemm<1, true,  true >, cudaFuncAttributeMaxDynamicSharedMemorySize, DYNSMEM);
    cudaFuncSetAttribute(bgemm<2, false, false>, cudaFuncAttributeMaxDynamicSharedMemorySize, DYNSMEM);
    cudaFuncSetAttribute(bgemm<0, false, false>, cudaFuncAttributeMaxDynamicSharedMemorySize, DYNSMEM);
    cudaFuncSetAttribute(bgemm<0, true,  false>, cudaFuncAttributeMaxDynamicSharedMemorySize, DYNSMEM);

    const int mt = (N_NODES + 127) / 128;  // 391

    // ---- prep: splits + CSR build (independent of GEMM chain) ----
    {
        long long n4 = (long long)N_NODES * IN_SIZE / 4;
        split_x_kernel<<<(unsigned)((n4 + 255) / 256), 256>>>((const float4*)x, xhi, xlo, n4);
    }
    split_w_kernel<false><<<(EMBP * IN_SIZE + 255) / 256, 256>>>(
        wenc, wenchi, wenclo, EMB, IN_SIZE, EMBP, IN_SIZE);
    split_w_kernel<true><<<(EMBP * EMBP + 255) / 256, 256>>>(
        conv_weight, convthi, convtlo, EMB, EMB, EMBP, EMBP);
    split_w_kernel<false><<<(EMBP * EMBP + 255) / 256, 256>>>(
        lin_weight, linhi, linlo, EMB, EMB, EMBP, EMBP);
    split_w_kernel<false><<<(IN_SIZE * EMBP + 255) / 256, 256>>>(
        wdec, wdechi, wdeclo, IN_SIZE, EMB, IN_SIZE, EMBP);

    k_zero_cnt<<<(N_NODES + 1 + 255) / 256, 256>>>();
    k_count<<<(N_EDGES + 255) / 256, 256>>>(edge_index);
    k_scan<<<1, SCAN_T>>>();
    k_fill<<<(N_EDGES + 255) / 256, 256>>>(edge_index, edge_weight);

    // 1) h = sigmoid(x @ wenc^T + benc) -> bf16 hi/lo pair
    {
        dim3 grid(EMBP / 128, mt);
        bgemm<1, true, true><<<grid, 256, DYNSMEM>>>(
            xhi, xlo, IN_SIZE, wenchi, wenclo, IN_SIZE, benc,
            nullptr, nullptr, 0, hhi, hlo, EMBP, N_NODES, EMB, IN_SIZE);
    }
    // 2) h2 = h @ conv_weight -> fp16 (stride EMBP, pads zero)
    {
        dim3 grid(EMBP / 128, mt);
        bgemm<2, false, false><<<grid, 256, DYNSMEM>>>(
            hhi, hlo, EMBP, convthi, convtlo, EMBP, nullptr,
            nullptr, h2h, EMBP, nullptr, nullptr, 0, N_NODES, EMB, EMBP);
    }
    // 3) agg = h @ lin_weight^T (fp32 lin term, pads zero)
    {
        dim3 grid(EMBP / 128, mt);
        bgemm<0, false, false><<<grid, 256, DYNSMEM>>>(
            hhi, hlo, EMBP, linhi, linlo, EMBP, nullptr,
            agg, nullptr, EMBP, nullptr, nullptr, 0, N_NODES, EMB, EMBP);
    }
    // 4) gather (CSR, no atomics, fp16 h2) + fused bf16 split of final agg
    gather_nodes<<<N_NODES, 128>>>(h2h, agg, agghi, agglo);
    // 5) out = agg @ wdec^T + bdec (fp32)
    {
        dim3 grid(IN_SIZE / 128, mt);
        bgemm<0, true, false><<<grid, 256, DYNSMEM>>>(
            agghi, agglo, EMBP, wdechi, wdeclo, EMBP, bdec,
            out, nullptr, IN_SIZE, nullptr, nullptr, 0, N_NODES, IN_SIZE, EMBP);
    }
}

// round 11
// speedup vs baseline: 5.1295x; 2.2552x over previous
#include <cuda_runtime.h>
#include <cuda_fp16.h>
#include <cstdint>

#define N_NODES 50000
#define N_EDGES 800000
#define IN_SIZE 1024
#define EMB 500
#define EMBP 512

// ---------------------------------------------------------------------------
// Scratch (device globals: allocation-free per harness rules)
// ---------------------------------------------------------------------------
__device__ __half g_xh[(size_t)N_NODES * IN_SIZE];     // x -> fp16
__device__ __half g_h[(size_t)N_NODES * EMBP];         // sigmoid(enc) fp16
__device__ __half g_h2h[(size_t)N_NODES * EMBP];       // conv output fp16
__device__ float  g_agg[(size_t)N_NODES * EMBP];       // lin term fp32
__device__ __half g_aggh[(size_t)N_NODES * EMBP];      // final agg fp16
// fp16 weights, padded [NP][Kp], K contiguous
__device__ __half g_wench[EMBP * IN_SIZE];
__device__ __half g_convth[EMBP * EMBP];
__device__ __half g_linh[EMBP * EMBP];
__device__ __half g_wdech[IN_SIZE * EMBP];
// CSR scratch
__device__ int   g_cnt[N_NODES + 1];
__device__ int   g_cur[N_NODES];
__device__ int   g_esrc[N_EDGES];
__device__ float g_ewt[N_EDGES];

// ---------------------------------------------------------------------------
// Convert kernels
// ---------------------------------------------------------------------------
__global__ __launch_bounds__(256) void convert_x_kernel(
    const float4* __restrict__ x, __half* __restrict__ xh, long long n4)
{
    long long i = (long long)blockIdx.x * blockDim.x + threadIdx.x;
    if (i >= n4) return;
    float4 v = x[i];
    __half2* p = reinterpret_cast<__half2*>(xh) + i * 2;
    p[0] = __floats2half2_rn(v.x, v.y);
    p[1] = __floats2half2_rn(v.z, v.w);
}

template <bool TRANS>
__global__ __launch_bounds__(256) void convert_w_kernel(
    const float* __restrict__ src, __half* __restrict__ dst,
    int N, int K, int NP, int Kp)
{
    int idx = blockIdx.x * blockDim.x + threadIdx.x;
    if (idx >= NP * Kp) return;
    int n = idx / Kp, k = idx - n * Kp;
    float v = 0.f;
    if (n < N && k < K)
        v = TRANS ? src[(long long)k * N + n] : src[(long long)n * K + k];
    dst[idx] = __float2half_rn(v);
}

// ---------------------------------------------------------------------------
// CSR build kernels
// ---------------------------------------------------------------------------
__global__ __launch_bounds__(256) void k_zero_cnt()
{
    int i = blockIdx.x * blockDim.x + threadIdx.x;
    if (i <= N_NODES) g_cnt[i] = 0;
}
__global__ __launch_bounds__(256) void k_count(const int* __restrict__ edge_index)
{
    int e = blockIdx.x * blockDim.x + threadIdx.x;
    if (e < N_EDGES) atomicAdd(&g_cnt[edge_index[N_EDGES + e]], 1);
}
#define SCAN_T 1024
#define SCAN_C 49   // 1024*49 = 50176 >= 50000
__global__ __launch_bounds__(SCAN_T) void k_scan()
{
    __shared__ int sh[SCAN_T];
    const int t = threadIdx.x;
    const int base = t * SCAN_C;
    int s = 0;
    #pragma unroll 4
    for (int j = 0; j < SCAN_C; j++) {
        int idx = base + j;
        if (idx < N_NODES) s += g_cnt[idx];
    }
    sh[t] = s;
    __syncthreads();
    for (int off = 1; off < SCAN_T; off <<= 1) {
        int v = (t >= off) ? sh[t - off] : 0;
        __syncthreads();
        sh[t] += v;
        __syncthreads();
    }
    int run = sh[t] - s;  // exclusive prefix
    for (int j = 0; j < SCAN_C; j++) {
        int idx = base + j;
        if (idx < N_NODES) {
            int c = g_cnt[idx];
            g_cnt[idx] = run;
            g_cur[idx] = run;
            run += c;
        }
    }
    if (t == 0) g_cnt[N_NODES] = N_EDGES;
}
__global__ __launch_bounds__(256) void k_fill(
    const int* __restrict__ edge_index, const float* __restrict__ ew)
{
    int e = blockIdx.x * blockDim.x + threadIdx.x;
    if (e >= N_EDGES) return;
    int dst = edge_index[N_EDGES + e];
    int pos = atomicAdd(&g_cur[dst], 1);
    g_esrc[pos] = edge_index[e];
    g_ewt[pos]  = ew[e];
}

// ---------------------------------------------------------------------------
// Gather (no atomics): acc = agg_lin[n] + sum_e w_e * h2[src_e]; out fp16.
// ---------------------------------------------------------------------------
__global__ __launch_bounds__(128) void gather_nodes(
    const __half* __restrict__ h2h, const float* __restrict__ agg,
    __half* __restrict__ aggh)
{
    const int n = blockIdx.x;
    const int c = threadIdx.x * 4;   // 0..508
    const int beg = g_cnt[n], end = g_cnt[n + 1];
    float4 acc = *reinterpret_cast<const float4*>(&agg[(long long)n * EMBP + c]);

    int e = beg;
    for (; e + 1 < end; e += 2) {
        const int   s0 = g_esrc[e],     s1 = g_esrc[e + 1];
        const float w0 = g_ewt[e],      w1 = g_ewt[e + 1];
        const __half2* p0 = reinterpret_cast<const __half2*>(h2h + (long long)s0 * EMBP + c);
        const __half2* p1 = reinterpret_cast<const __half2*>(h2h + (long long)s1 * EMBP + c);
        const __half2 a0 = p0[0], a1 = p0[1];
        const __half2 b0 = p1[0], b1 = p1[1];
        float2 f0 = __half22float2(a0), f1 = __half22float2(a1);
        float2 f2 = __half22float2(b0), f3 = __half22float2(b1);
        acc.x = fmaf(f0.x, w0, acc.x); acc.y = fmaf(f0.y, w0, acc.y);
        acc.z = fmaf(f1.x, w0, acc.z); acc.w = fmaf(f1.y, w0, acc.w);
        acc.x = fmaf(f2.x, w1, acc.x); acc.y = fmaf(f2.y, w1, acc.y);
        acc.z = fmaf(f3.x, w1, acc.z); acc.w = fmaf(f3.y, w1, acc.w);
    }
    if (e < end) {
        const int   s0 = g_esrc[e];
        const float w0 = g_ewt[e];
        const __half2* p0 = reinterpret_cast<const __half2*>(h2h + (long long)s0 * EMBP + c);
        float2 f0 = __half22float2(p0[0]), f1 = __half22float2(p0[1]);
        acc.x = fmaf(f0.x, w0, acc.x); acc.y = fmaf(f0.y, w0, acc.y);
        acc.z = fmaf(f1.x, w0, acc.z); acc.w = fmaf(f1.y, w0, acc.w);
    }

    __half2* po = reinterpret_cast<__half2*>(aggh + (long long)n * EMBP + c);
    po[0] = __floats2half2_rn(acc.x, acc.y);
    po[1] = __floats2half2_rn(acc.z, acc.w);
}

// ---------------------------------------------------------------------------
// Single-term fp16 GEMM, mma.sync m16n8k16 + cp.async 3-stage pipeline.
// C[M,N] = act(A[M,K] @ B[N,K]^T + bias). BM=BN=128, BK=32, 256 thr, 2 CTA/SM.
// smem rows padded to 40 halves (80B stride; ldsm phase-conflict-free).
// OMODE: 0 = fp32 out, 2 = fp16 out. K mult of 32, B rows padded (NP).
// ---------------------------------------------------------------------------
#define KPAD 40
#define TILE_BYTES (128 * KPAD * 2)        // 10240 per matrix
#define STAGE_BYTES (2 * TILE_BYTES)       // 20480
#define NSTAGE 3
#define DYNSMEM (NSTAGE * STAGE_BYTES)     // 61440 -> 2 CTAs/SM

__device__ __forceinline__ void ldsm4(uint32_t (&r)[4], uint32_t addr) {
    asm volatile("ldmatrix.sync.aligned.m8n8.x4.shared.b16 {%0,%1,%2,%3}, [%4];"
                 : "=r"(r[0]), "=r"(r[1]), "=r"(r[2]), "=r"(r[3]) : "r"(addr));
}
__device__ __forceinline__ void mma_f16(float (&c)[4], const uint32_t (&a)[4],
                                        uint32_t b0, uint32_t b1) {
    asm volatile(
        "mma.sync.aligned.m16n8k16.row.col.f32.f16.f16.f32 "
        "{%0,%1,%2,%3}, {%4,%5,%6,%7}, {%8,%9}, {%0,%1,%2,%3};"
        : "+f"(c[0]), "+f"(c[1]), "+f"(c[2]), "+f"(c[3])
        : "r"(a[0]), "r"(a[1]), "r"(a[2]), "r"(a[3]), "r"(b0), "r"(b1));
}
__device__ __forceinline__ void cpa16(uint32_t dst, const void* src, int sz) {
    asm volatile("cp.async.cg.shared.global [%0], [%1], 16, %2;"
                 :: "r"(dst), "l"(src), "r"(sz) : "memory");
}
__device__ __forceinline__ void cpa16u(uint32_t dst, const void* src) {
    asm volatile("cp.async.cg.shared.global [%0], [%1], 16;"
                 :: "r"(dst), "l"(src) : "memory");
}

template <int OMODE, bool BIAS, bool SIG>
__global__ __launch_bounds__(256, 2) void hgemm(
    const __half* __restrict__ A, int sA_,
    const __half* __restrict__ B, int sB_,
    const float* __restrict__ bias,
    float* __restrict__ C, __half* __restrict__ Ch, int sC,
    int M, int Nreal, int K)
{
    extern __shared__ char smem[];

    const int tid  = threadIdx.x;
    const int lane = tid & 31;
    const int warp = tid >> 5;
    const int wm = warp >> 1;   // 0..3
    const int wn = warp & 1;    // 0..1
    const int m0 = blockIdx.y * 128;
    const int n0 = blockIdx.x * 128;

    // cp.async mapping: 2 threads/row; each copies 2x16B chunks of 64B row
    const int lrow = tid >> 1;
    const int cp0  = (tid & 1) * 2;        // chunk 0 or 2
    const int gmA  = m0 + lrow;
    const int szA  = (gmA < M) ? 16 : 0;
    const __half* srcA = A + (long long)gmA * sA_ + cp0 * 8;
    const __half* srcB = B + (long long)(n0 + lrow) * sB_ + cp0 * 8;
    const uint32_t smem_u = (uint32_t)__cvta_generic_to_shared(smem);
    const uint32_t dRow = (uint32_t)(lrow * (KPAD * 2) + cp0 * 16);

    float acc[2][8][4];
    #pragma unroll
    for (int i = 0; i < 2; i++)
        #pragma unroll
        for (int j = 0; j < 8; j++)
            #pragma unroll
            for (int e = 0; e < 4; e++) acc[i][j][e] = 0.f;

    const int g = lane >> 3, r8 = lane & 7;
    const int nk = K / 32;

    auto load_stage = [&](int st, int k0) {
        const uint32_t aBase = smem_u + st * STAGE_BYTES + dRow;
        const uint32_t bBase = aBase + TILE_BYTES;
        cpa16(aBase,      srcA + k0, szA);
        cpa16(aBase + 16, srcA + k0 + 8, szA);
        cpa16u(bBase,      srcB + k0);
        cpa16u(bBase + 16, srcB + k0 + 8);
        asm volatile("cp.async.commit_group;" ::: "memory");
    };

    load_stage(0, 0);
    load_stage(1, 32);

    // ldsm address bases (bytes, within tile)
    const int aRowBase = wm * 32 + (g & 1) * 8 + r8;
    const int aColB    = (g >> 1) * 16;
    const int bRowBase = wn * 64 + (g >> 1) * 8 + r8;
    const int bColB    = (g & 1) * 16;

    for (int s = 0; s < nk; s++) {
        if (s + 1 < nk) { asm volatile("cp.async.wait_group 1;" ::: "memory"); }
        else            { asm volatile("cp.async.wait_group 0;" ::: "memory"); }
        __syncthreads();
        if (s + 2 < nk) load_stage((s + 2) % NSTAGE, (s + 2) * 32);

        const uint32_t aBuf = smem_u + (s % NSTAGE) * STAGE_BYTES;
        const uint32_t bBuf = aBuf + TILE_BYTES;

        #pragma unroll
        for (int ks = 0; ks < 2; ks++) {
            const int kkB = ks * 32;   // 16 halves
            uint32_t a[2][4];
            #pragma unroll
            for (int mt = 0; mt < 2; mt++)
                ldsm4(a[mt], aBuf + (uint32_t)((aRowBase + mt * 16) * (KPAD * 2)
                                               + kkB + aColB));
            #pragma unroll
            for (int p = 0; p < 4; p++) {
                uint32_t b[4];
                ldsm4(b, bBuf + (uint32_t)((bRowBase + p * 16) * (KPAD * 2)
                                           + kkB + bColB));
                #pragma unroll
                for (int sx = 0; sx < 2; sx++)
                    #pragma unroll
                    for (int mt = 0; mt < 2; mt++)
                        mma_f16(acc[mt][p * 2 + sx], a[mt],
                                b[sx * 2], b[sx * 2 + 1]);
            }
        }
    }

    // ---- epilogue ----
    const int rq = lane >> 2, cq = (lane & 3) * 2;
    #pragma unroll
    for (int mt = 0; mt < 2; mt++)
        #pragma unroll
        for (int nt = 0; nt < 8; nt++) {
            const int gr0 = m0 + wm * 32 + mt * 16 + rq;
            const int gc0 = n0 + wn * 64 + nt * 8 + cq;
            #pragma unroll
            for (int e = 0; e < 4; e++) {
                const int gm = gr0 + (e >> 1) * 8;
                const int gn = gc0 + (e & 1);
                if (gm >= M) continue;
                float v = acc[mt][nt][e];
                if (gn < Nreal) {
                    if (BIAS) v += bias[gn];
                    if (SIG) v = 1.f / (1.f + expf(-v));
                } else {
                    v = 0.f;   // pad columns
                }
                if (OMODE == 2) {
                    Ch[(long long)gm * sC + gn] = __float2half_rn(v);
                } else {
                    C[(long long)gm * sC + gn] = v;
                }
            }
        }
}

// ---------------------------------------------------------------------------
extern "C" void kernel_launch(void* const* d_in, const int* in_sizes, int n_in,
                              void* d_out, int out_size)
{
    const float* x           = (const float*)d_in[0];
    const int*   edge_index  = (const int*)  d_in[1];
    const float* edge_weight = (const float*)d_in[2];
    const float* wenc        = (const float*)d_in[3];  // [EMB, IN_SIZE]
    const float* benc        = (const float*)d_in[4];
    const float* wdec        = (const float*)d_in[5];  // [IN_SIZE, EMB]
    const float* bdec        = (const float*)d_in[6];
    const float* conv_weight = (const float*)d_in[7];  // [EMB, EMB] (k, n)
    const float* lin_weight  = (const float*)d_in[8];  // [EMB, EMB] (n, k)
    float* out = (float*)d_out;

    __half *xh, *h, *h2h, *aggh, *wench, *convth, *linh, *wdech;
    float *agg;
    cudaGetSymbolAddress((void**)&xh, g_xh);
    cudaGetSymbolAddress((void**)&h, g_h);
    cudaGetSymbolAddress((void**)&h2h, g_h2h);
    cudaGetSymbolAddress((void**)&aggh, g_aggh);
    cudaGetSymbolAddress((void**)&agg, g_agg);
    cudaGetSymbolAddress((void**)&wench, g_wench);
    cudaGetSymbolAddress((void**)&convth, g_convth);
    cudaGetSymbolAddress((void**)&linh, g_linh);
    cudaGetSymbolAddress((void**)&wdech, g_wdech);

    cudaFuncSetAttribute(hgemm<2, true,  true >, cudaFuncAttributeMaxDynamicSharedMemorySize, DYNSMEM);
    cudaFuncSetAttribute(hgemm<2, false, false>, cudaFuncAttributeMaxDynamicSharedMemorySize, DYNSMEM);
    cudaFuncSetAttribute(hgemm<0, false, false>, cudaFuncAttributeMaxDynamicSharedMemorySize, DYNSMEM);
    cudaFuncSetAttribute(hgemm<0, true,  false>, cudaFuncAttributeMaxDynamicSharedMemorySize, DYNSMEM);

    const int mt = (N_NODES + 127) / 128;  // 391

    // ---- prep: converts + CSR build ----
    {
        long long n4 = (long long)N_NODES * IN_SIZE / 4;
        convert_x_kernel<<<(unsigned)((n4 + 255) / 256), 256>>>((const float4*)x, xh, n4);
    }
    convert_w_kernel<false><<<(EMBP * IN_SIZE + 255) / 256, 256>>>(
        wenc, wench, EMB, IN_SIZE, EMBP, IN_SIZE);
    convert_w_kernel<true><<<(EMBP * EMBP + 255) / 256, 256>>>(
        conv_weight, convth, EMB, EMB, EMBP, EMBP);
    convert_w_kernel<false><<<(EMBP * EMBP + 255) / 256, 256>>>(
        lin_weight, linh, EMB, EMB, EMBP, EMBP);
    convert_w_kernel<false><<<(IN_SIZE * EMBP + 255) / 256, 256>>>(
        wdec, wdech, IN_SIZE, EMB, IN_SIZE, EMBP);

    k_zero_cnt<<<(N_NODES + 1 + 255) / 256, 256>>>();
    k_count<<<(N_EDGES + 255) / 256, 256>>>(edge_index);
    k_scan<<<1, SCAN_T>>>();
    k_fill<<<(N_EDGES + 255) / 256, 256>>>(edge_index, edge_weight);

    // 1) h = sigmoid(x @ wenc^T + benc) -> fp16 (stride EMBP)
    {
        dim3 grid(EMBP / 128, mt);
        hgemm<2, true, true><<<grid, 256, DYNSMEM>>>(
            xh, IN_SIZE, wench, IN_SIZE, benc,
            nullptr, h, EMBP, N_NODES, EMB, IN_SIZE);
    }
    // 2) h2 = h @ conv_weight -> fp16 (pads zero)
    {
        dim3 grid(EMBP / 128, mt);
        hgemm<2, false, false><<<grid, 256, DYNSMEM>>>(
            h, EMBP, convth, EMBP, nullptr,
            nullptr, h2h, EMBP, N_NODES, EMB, EMBP);
    }
    // 3) agg = h @ lin_weight^T -> fp32 lin term (pads zero)
    {
        dim3 grid(EMBP / 128, mt);
        hgemm<0, false, false><<<grid, 256, DYNSMEM>>>(
            h, EMBP, linh, EMBP, nullptr,
            agg, nullptr, EMBP, N_NODES, EMB, EMBP);
    }
    // 4) gather (CSR, no atomics) -> aggh fp16
    gather_nodes<<<N_NODES, 128>>>(h2h, agg, aggh);
    // 5) out = aggh @ wdec^T + bdec (fp32)
    {
        dim3 grid(IN_SIZE / 128, mt);
        hgemm<0, true, false><<<grid, 256, DYNSMEM>>>(
            aggh, EMBP, wdech, EMBP, bdec,
            out, nullptr, IN_SIZE, N_NODES, IN_SIZE, EMBP);
    }
}

// round 12
// speedup vs baseline: 5.6607x; 1.1036x over previous
#include <cuda_runtime.h>
#include <cuda_fp16.h>
#include <cstdint>

#define N_NODES 50000
#define N_EDGES 800000
#define IN_SIZE 1024
#define EMB 500
#define EMBP 512
#define CLW 1024   // combined conv|lin output width

// ---------------------------------------------------------------------------
// Scratch (device globals: allocation-free per harness rules)
// ---------------------------------------------------------------------------
__device__ __half g_xh[(size_t)N_NODES * IN_SIZE];     // x -> fp16
__device__ __half g_h[(size_t)N_NODES * EMBP];         // sigmoid(enc) fp16
__device__ __half g_hw[(size_t)N_NODES * CLW];         // [h2 | agg_lin] fp16
__device__ __half g_aggh[(size_t)N_NODES * EMBP];      // final agg fp16
// fp16 weights, padded [NP][Kp], K contiguous
__device__ __half g_wench[EMBP * IN_SIZE];
__device__ __half g_clh[CLW * EMBP];                   // [conv^T ; lin] stacked
__device__ __half g_wdech[IN_SIZE * EMBP];
// CSR scratch
__device__ int   g_cnt[N_NODES + 1];
__device__ int   g_cur[N_NODES];
__device__ int   g_esrc[N_EDGES];
__device__ float g_ewt[N_EDGES];

// ---------------------------------------------------------------------------
// Convert kernels
// ---------------------------------------------------------------------------
__global__ __launch_bounds__(256) void convert_x_kernel(
    const float4* __restrict__ x, __half* __restrict__ xh, long long n4)
{
    long long i = (long long)blockIdx.x * blockDim.x + threadIdx.x;
    if (i >= n4) return;
    float4 v = x[i];
    __half2* p = reinterpret_cast<__half2*>(xh) + i * 2;
    p[0] = __floats2half2_rn(v.x, v.y);
    p[1] = __floats2half2_rn(v.z, v.w);
}

template <bool TRANS>
__global__ __launch_bounds__(256) void convert_w_kernel(
    const float* __restrict__ src, __half* __restrict__ dst,
    int N, int K, int NP, int Kp)
{
    int idx = blockIdx.x * blockDim.x + threadIdx.x;
    if (idx >= NP * Kp) return;
    int n = idx / Kp, k = idx - n * Kp;
    float v = 0.f;
    if (n < N && k < K)
        v = TRANS ? src[(long long)k * N + n] : src[(long long)n * K + k];
    dst[idx] = __float2half_rn(v);
}

// ---------------------------------------------------------------------------
// CSR build kernels
// ---------------------------------------------------------------------------
__global__ __launch_bounds__(256) void k_zero_cnt()
{
    int i = blockIdx.x * blockDim.x + threadIdx.x;
    if (i <= N_NODES) g_cnt[i] = 0;
}
__global__ __launch_bounds__(256) void k_count(const int* __restrict__ edge_index)
{
    int e = blockIdx.x * blockDim.x + threadIdx.x;
    if (e < N_EDGES) atomicAdd(&g_cnt[edge_index[N_EDGES + e]], 1);
}
#define SCAN_T 1024
#define SCAN_C 49   // 1024*49 = 50176 >= 50000
__global__ __launch_bounds__(SCAN_T) void k_scan()
{
    __shared__ int sh[SCAN_T];
    const int t = threadIdx.x;
    const int base = t * SCAN_C;
    int s = 0;
    #pragma unroll 4
    for (int j = 0; j < SCAN_C; j++) {
        int idx = base + j;
        if (idx < N_NODES) s += g_cnt[idx];
    }
    sh[t] = s;
    __syncthreads();
    for (int off = 1; off < SCAN_T; off <<= 1) {
        int v = (t >= off) ? sh[t - off] : 0;
        __syncthreads();
        sh[t] += v;
        __syncthreads();
    }
    int run = sh[t] - s;  // exclusive prefix
    for (int j = 0; j < SCAN_C; j++) {
        int idx = base + j;
        if (idx < N_NODES) {
            int c = g_cnt[idx];
            g_cnt[idx] = run;
            g_cur[idx] = run;
            run += c;
        }
    }
    if (t == 0) g_cnt[N_NODES] = N_EDGES;
}
__global__ __launch_bounds__(256) void k_fill(
    const int* __restrict__ edge_index, const float* __restrict__ ew)
{
    int e = blockIdx.x * blockDim.x + threadIdx.x;
    if (e >= N_EDGES) return;
    int dst = edge_index[N_EDGES + e];
    int pos = atomicAdd(&g_cur[dst], 1);
    g_esrc[pos] = edge_index[e];
    g_ewt[pos]  = ew[e];
}

// ---------------------------------------------------------------------------
// Gather (no atomics): acc = lin_part[n] + sum_e w_e * h2_part[src_e].
// hw layout: row n = [h2 (512 fp16) | agg_lin (512 fp16)]. Unroll 4 for MLP.
// ---------------------------------------------------------------------------
__global__ __launch_bounds__(128) void gather_nodes(
    const __half* __restrict__ hw, __half* __restrict__ aggh)
{
    const int n = blockIdx.x;
    const int c = threadIdx.x * 4;   // 0..508
    const int beg = g_cnt[n], end = g_cnt[n + 1];

    // base = lin part (cols 512..1023)
    const __half2* pb = reinterpret_cast<const __half2*>(
        hw + (long long)n * CLW + EMBP + c);
    float2 b0 = __half22float2(pb[0]), b1 = __half22float2(pb[1]);
    float4 acc = make_float4(b0.x, b0.y, b1.x, b1.y);

    int e = beg;
    for (; e + 3 < end; e += 4) {
        int   s0 = g_esrc[e],   s1 = g_esrc[e+1], s2 = g_esrc[e+2], s3 = g_esrc[e+3];
        float w0 = g_ewt[e],    w1 = g_ewt[e+1],  w2 = g_ewt[e+2],  w3 = g_ewt[e+3];
        const __half2* p0 = reinterpret_cast<const __half2*>(hw + (long long)s0 * CLW + c);
        const __half2* p1 = reinterpret_cast<const __half2*>(hw + (long long)s1 * CLW + c);
        const __half2* p2 = reinterpret_cast<const __half2*>(hw + (long long)s2 * CLW + c);
        const __half2* p3 = reinterpret_cast<const __half2*>(hw + (long long)s3 * CLW + c);
        __half2 a00 = p0[0], a01 = p0[1];
        __half2 a10 = p1[0], a11 = p1[1];
        __half2 a20 = p2[0], a21 = p2[1];
        __half2 a30 = p3[0], a31 = p3[1];
        float2 f;
        f = __half22float2(a00); acc.x = fmaf(f.x, w0, acc.x); acc.y = fmaf(f.y, w0, acc.y);
        f = __half22float2(a01); acc.z = fmaf(f.x, w0, acc.z); acc.w = fmaf(f.y, w0, acc.w);
        f = __half22float2(a10); acc.x = fmaf(f.x, w1, acc.x); acc.y = fmaf(f.y, w1, acc.y);
        f = __half22float2(a11); acc.z = fmaf(f.x, w1, acc.z); acc.w = fmaf(f.y, w1, acc.w);
        f = __half22float2(a20); acc.x = fmaf(f.x, w2, acc.x); acc.y = fmaf(f.y, w2, acc.y);
        f = __half22float2(a21); acc.z = fmaf(f.x, w2, acc.z); acc.w = fmaf(f.y, w2, acc.w);
        f = __half22float2(a30); acc.x = fmaf(f.x, w3, acc.x); acc.y = fmaf(f.y, w3, acc.y);
        f = __half22float2(a31); acc.z = fmaf(f.x, w3, acc.z); acc.w = fmaf(f.y, w3, acc.w);
    }
    for (; e < end; e++) {
        int   s0 = g_esrc[e];
        float w0 = g_ewt[e];
        const __half2* p0 = reinterpret_cast<const __half2*>(hw + (long long)s0 * CLW + c);
        float2 f0 = __half22float2(p0[0]), f1 = __half22float2(p0[1]);
        acc.x = fmaf(f0.x, w0, acc.x); acc.y = fmaf(f0.y, w0, acc.y);
        acc.z = fmaf(f1.x, w0, acc.z); acc.w = fmaf(f1.y, w0, acc.w);
    }

    __half2* po = reinterpret_cast<__half2*>(aggh + (long long)n * EMBP + c);
    po[0] = __floats2half2_rn(acc.x, acc.y);
    po[1] = __floats2half2_rn(acc.z, acc.w);
}

// ---------------------------------------------------------------------------
// Single-term fp16 GEMM, mma.sync m16n8k16 + cp.async 3-stage pipeline.
// C[M,N] = act(A[M,K] @ B[N,K]^T + bias). BM=BN=128, BK=32, 256 thr, 2 CTA/SM.
// smem rows padded to 40 halves (80B stride; conflict-free ldmatrix).
// OMODE: 0 = fp32 out, 2 = fp16 out. K mult of 32, B rows padded (NP).
// Pad output cols are zero automatically when B pad rows are zero & !BIAS;
// with BIAS/SIG the gn<Nreal guard zeroes them explicitly.
// ---------------------------------------------------------------------------
#define KPAD 40
#define TILE_BYTES (128 * KPAD * 2)        // 10240 per matrix
#define STAGE_BYTES (2 * TILE_BYTES)       // 20480
#define NSTAGE 3
#define DYNSMEM (NSTAGE * STAGE_BYTES)     // 61440 -> 2 CTAs/SM

__device__ __forceinline__ void ldsm4(uint32_t (&r)[4], uint32_t addr) {
    asm volatile("ldmatrix.sync.aligned.m8n8.x4.shared.b16 {%0,%1,%2,%3}, [%4];"
                 : "=r"(r[0]), "=r"(r[1]), "=r"(r[2]), "=r"(r[3]) : "r"(addr));
}
__device__ __forceinline__ void mma_f16(float (&c)[4], const uint32_t (&a)[4],
                                        uint32_t b0, uint32_t b1) {
    asm volatile(
        "mma.sync.aligned.m16n8k16.row.col.f32.f16.f16.f32 "
        "{%0,%1,%2,%3}, {%4,%5,%6,%7}, {%8,%9}, {%0,%1,%2,%3};"
        : "+f"(c[0]), "+f"(c[1]), "+f"(c[2]), "+f"(c[3])
        : "r"(a[0]), "r"(a[1]), "r"(a[2]), "r"(a[3]), "r"(b0), "r"(b1));
}
__device__ __forceinline__ void cpa16(uint32_t dst, const void* src, int sz) {
    asm volatile("cp.async.cg.shared.global [%0], [%1], 16, %2;"
                 :: "r"(dst), "l"(src), "r"(sz) : "memory");
}
__device__ __forceinline__ void cpa16u(uint32_t dst, const void* src) {
    asm volatile("cp.async.cg.shared.global [%0], [%1], 16;"
                 :: "r"(dst), "l"(src) : "memory");
}

template <int OMODE, bool BIAS, bool SIG>
__global__ __launch_bounds__(256, 2) void hgemm(
    const __half* __restrict__ A, int sA_,
    const __half* __restrict__ B, int sB_,
    const float* __restrict__ bias,
    float* __restrict__ C, __half* __restrict__ Ch, int sC,
    int M, int Nreal, int K)
{
    extern __shared__ char smem[];

    const int tid  = threadIdx.x;
    const int lane = tid & 31;
    const int warp = tid >> 5;
    const int wm = warp >> 1;   // 0..3
    const int wn = warp & 1;    // 0..1
    const int m0 = blockIdx.y * 128;
    const int n0 = blockIdx.x * 128;

    const int lrow = tid >> 1;
    const int cp0  = (tid & 1) * 2;
    const int gmA  = m0 + lrow;
    const int szA  = (gmA < M) ? 16 : 0;
    const __half* srcA = A + (long long)gmA * sA_ + cp0 * 8;
    const __half* srcB = B + (long long)(n0 + lrow) * sB_ + cp0 * 8;
    const uint32_t smem_u = (uint32_t)__cvta_generic_to_shared(smem);
    const uint32_t dRow = (uint32_t)(lrow * (KPAD * 2) + cp0 * 16);

    float acc[2][8][4];
    #pragma unroll
    for (int i = 0; i < 2; i++)
        #pragma unroll
        for (int j = 0; j < 8; j++)
            #pragma unroll
            for (int e = 0; e < 4; e++) acc[i][j][e] = 0.f;

    const int g = lane >> 3, r8 = lane & 7;
    const int nk = K / 32;

    auto load_stage = [&](int st, int k0) {
        const uint32_t aBase = smem_u + st * STAGE_BYTES + dRow;
        const uint32_t bBase = aBase + TILE_BYTES;
        cpa16(aBase,      srcA + k0, szA);
        cpa16(aBase + 16, srcA + k0 + 8, szA);
        cpa16u(bBase,      srcB + k0);
        cpa16u(bBase + 16, srcB + k0 + 8);
        asm volatile("cp.async.commit_group;" ::: "memory");
    };

    load_stage(0, 0);
    load_stage(1, 32);

    const int aRowBase = wm * 32 + (g & 1) * 8 + r8;
    const int aColB    = (g >> 1) * 16;
    const int bRowBase = wn * 64 + (g >> 1) * 8 + r8;
    const int bColB    = (g & 1) * 16;

    for (int s = 0; s < nk; s++) {
        if (s + 1 < nk) { asm volatile("cp.async.wait_group 1;" ::: "memory"); }
        else            { asm volatile("cp.async.wait_group 0;" ::: "memory"); }
        __syncthreads();
        if (s + 2 < nk) load_stage((s + 2) % NSTAGE, (s + 2) * 32);

        const uint32_t aBuf = smem_u + (s % NSTAGE) * STAGE_BYTES;
        const uint32_t bBuf = aBuf + TILE_BYTES;

        #pragma unroll
        for (int ks = 0; ks < 2; ks++) {
            const int kkB = ks * 32;
            uint32_t a[2][4];
            #pragma unroll
            for (int mt = 0; mt < 2; mt++)
                ldsm4(a[mt], aBuf + (uint32_t)((aRowBase + mt * 16) * (KPAD * 2)
                                               + kkB + aColB));
            #pragma unroll
            for (int p = 0; p < 4; p++) {
                uint32_t b[4];
                ldsm4(b, bBuf + (uint32_t)((bRowBase + p * 16) * (KPAD * 2)
                                           + kkB + bColB));
                #pragma unroll
                for (int sx = 0; sx < 2; sx++)
                    #pragma unroll
                    for (int mt = 0; mt < 2; mt++)
                        mma_f16(acc[mt][p * 2 + sx], a[mt],
                                b[sx * 2], b[sx * 2 + 1]);
            }
        }
    }

    // ---- epilogue: packed stores (e-pairs are adjacent columns) ----
    const int rq = lane >> 2, cq = (lane & 3) * 2;
    #pragma unroll
    for (int mt = 0; mt < 2; mt++)
        #pragma unroll
        for (int nt = 0; nt < 8; nt++) {
            const int gc = n0 + wn * 64 + nt * 8 + cq;   // even
            #pragma unroll
            for (int half_ : {0, 1}) {
                const int gm = m0 + wm * 32 + mt * 16 + rq + half_ * 8;
                if (gm >= M) continue;
                float v0 = acc[mt][nt][half_ * 2 + 0];
                float v1 = acc[mt][nt][half_ * 2 + 1];
                if (BIAS || SIG) {
                    if (gc < Nreal)     { if (BIAS) v0 += bias[gc]; }
                    else v0 = 0.f;
                    if (gc + 1 < Nreal) { if (BIAS) v1 += bias[gc + 1]; }
                    else v1 = 0.f;
                    if (SIG) {
                        if (gc < Nreal)     v0 = 1.f / (1.f + expf(-v0));
                        if (gc + 1 < Nreal) v1 = 1.f / (1.f + expf(-v1));
                    }
                }
                if (OMODE == 2) {
                    *reinterpret_cast<__half2*>(Ch + (long long)gm * sC + gc)
                        = __floats2half2_rn(v0, v1);
                } else {
                    *reinterpret_cast<float2*>(C + (long long)gm * sC + gc)
                        = make_float2(v0, v1);
                }
            }
        }
}

// ---------------------------------------------------------------------------
extern "C" void kernel_launch(void* const* d_in, const int* in_sizes, int n_in,
                              void* d_out, int out_size)
{
    const float* x           = (const float*)d_in[0];
    const int*   edge_index  = (const int*)  d_in[1];
    const float* edge_weight = (const float*)d_in[2];
    const float* wenc        = (const float*)d_in[3];  // [EMB, IN_SIZE]
    const float* benc        = (const float*)d_in[4];
    const float* wdec        = (const float*)d_in[5];  // [IN_SIZE, EMB]
    const float* bdec        = (const float*)d_in[6];
    const float* conv_weight = (const float*)d_in[7];  // [EMB, EMB] (k, n)
    const float* lin_weight  = (const float*)d_in[8];  // [EMB, EMB] (n, k)
    float* out = (float*)d_out;

    __half *xh, *h, *hw, *aggh, *wench, *clh, *wdech;
    cudaGetSymbolAddress((void**)&xh, g_xh);
    cudaGetSymbolAddress((void**)&h, g_h);
    cudaGetSymbolAddress((void**)&hw, g_hw);
    cudaGetSymbolAddress((void**)&aggh, g_aggh);
    cudaGetSymbolAddress((void**)&wench, g_wench);
    cudaGetSymbolAddress((void**)&clh, g_clh);
    cudaGetSymbolAddress((void**)&wdech, g_wdech);

    cudaFuncSetAttribute(hgemm<2, true,  true >, cudaFuncAttributeMaxDynamicSharedMemorySize, DYNSMEM);
    cudaFuncSetAttribute(hgemm<2, false, false>, cudaFuncAttributeMaxDynamicSharedMemorySize, DYNSMEM);
    cudaFuncSetAttribute(hgemm<0, true,  false>, cudaFuncAttributeMaxDynamicSharedMemorySize, DYNSMEM);

    const int mt = (N_NODES + 127) / 128;  // 391

    // ---- prep: converts + CSR build ----
    {
        long long n4 = (long long)N_NODES * IN_SIZE / 4;
        convert_x_kernel<<<(unsigned)((n4 + 255) / 256), 256>>>((const float4*)x, xh, n4);
    }
    convert_w_kernel<false><<<(EMBP * IN_SIZE + 255) / 256, 256>>>(
        wenc, wench, EMB, IN_SIZE, EMBP, IN_SIZE);
    // combined B: rows [0,512) = conv^T, rows [512,1024) = lin
    convert_w_kernel<true><<<(EMBP * EMBP + 255) / 256, 256>>>(
        conv_weight, clh, EMB, EMB, EMBP, EMBP);
    convert_w_kernel<false><<<(EMBP * EMBP + 255) / 256, 256>>>(
        lin_weight, clh + (size_t)EMBP * EMBP, EMB, EMB, EMBP, EMBP);
    convert_w_kernel<false><<<(IN_SIZE * EMBP + 255) / 256, 256>>>(
        wdec, wdech, IN_SIZE, EMB, IN_SIZE, EMBP);

    k_zero_cnt<<<(N_NODES + 1 + 255) / 256, 256>>>();
    k_count<<<(N_EDGES + 255) / 256, 256>>>(edge_index);
    k_scan<<<1, SCAN_T>>>();
    k_fill<<<(N_EDGES + 255) / 256, 256>>>(edge_index, edge_weight);

    // 1) h = sigmoid(x @ wenc^T + benc) -> fp16 (stride EMBP)
    {
        dim3 grid(EMBP / 128, mt);
        hgemm<2, true, true><<<grid, 256, DYNSMEM>>>(
            xh, IN_SIZE, wench, IN_SIZE, benc,
            nullptr, h, EMBP, N_NODES, EMB, IN_SIZE);
    }
    // 2) hw = h @ [conv^T ; lin]^T -> [h2 | agg_lin] fp16 (pads zero via B)
    {
        dim3 grid(CLW / 128, mt);
        hgemm<2, false, false><<<grid, 256, DYNSMEM>>>(
            h, EMBP, clh, EMBP, nullptr,
            nullptr, hw, CLW, N_NODES, CLW, EMBP);
    }
    // 3) gather (CSR, no atomics) -> aggh fp16
    gather_nodes<<<N_NODES, 128>>>(hw, aggh);
    // 4) out = aggh @ wdec^T + bdec (fp32)
    {
        dim3 grid(IN_SIZE / 128, mt);
        hgemm<0, true, false><<<grid, 256, DYNSMEM>>>(
            aggh, EMBP, wdech, EMBP, bdec,
            out, nullptr, IN_SIZE, N_NODES, IN_SIZE, EMBP);
    }
}

// round 13
// speedup vs baseline: 5.7997x; 1.0246x over previous
#include <cuda_runtime.h>
#include <cuda_fp16.h>
#include <cstdint>

#define N_NODES 50000
#define N_EDGES 800000
#define IN_SIZE 1024
#define EMB 500
#define EMBP 512
#define CLW 1024   // combined conv|lin output width

// ---------------------------------------------------------------------------
// Scratch (device globals: allocation-free per harness rules)
// ---------------------------------------------------------------------------
__device__ __half g_xh[(size_t)N_NODES * IN_SIZE];     // x -> fp16
__device__ __half g_h[(size_t)N_NODES * EMBP];         // sigmoid(enc) fp16
__device__ __half g_hw[(size_t)N_NODES * CLW];         // [h2 | agg_lin] fp16
__device__ __half g_aggh[(size_t)N_NODES * EMBP];      // final agg fp16
// fp16 weights, padded [NP][Kp], K contiguous
__device__ __half g_wench[EMBP * IN_SIZE];
__device__ __half g_clh[CLW * EMBP];                   // [conv^T ; lin] stacked
__device__ __half g_wdech[IN_SIZE * EMBP];
// CSR scratch
__device__ int   g_cnt[N_NODES + 1];
__device__ int   g_cur[N_NODES];
__device__ int   g_esrc[N_EDGES];
__device__ float g_ewt[N_EDGES];

// ---------------------------------------------------------------------------
// Convert kernels
// ---------------------------------------------------------------------------
__global__ __launch_bounds__(256) void convert_x_kernel(
    const float4* __restrict__ x, __half* __restrict__ xh, long long n4)
{
    long long i = (long long)blockIdx.x * blockDim.x + threadIdx.x;
    if (i >= n4) return;
    float4 v = x[i];
    __half2* p = reinterpret_cast<__half2*>(xh) + i * 2;
    p[0] = __floats2half2_rn(v.x, v.y);
    p[1] = __floats2half2_rn(v.z, v.w);
}

template <bool TRANS>
__global__ __launch_bounds__(256) void convert_w_kernel(
    const float* __restrict__ src, __half* __restrict__ dst,
    int N, int K, int NP, int Kp)
{
    int idx = blockIdx.x * blockDim.x + threadIdx.x;
    if (idx >= NP * Kp) return;
    int n = idx / Kp, k = idx - n * Kp;
    float v = 0.f;
    if (n < N && k < K)
        v = TRANS ? src[(long long)k * N + n] : src[(long long)n * K + k];
    dst[idx] = __float2half_rn(v);
}

// ---------------------------------------------------------------------------
// CSR build kernels
// ---------------------------------------------------------------------------
__global__ __launch_bounds__(256) void k_zero_cnt()
{
    int i = blockIdx.x * blockDim.x + threadIdx.x;
    if (i <= N_NODES) g_cnt[i] = 0;
}
__global__ __launch_bounds__(256) void k_count(const int* __restrict__ edge_index)
{
    int e = blockIdx.x * blockDim.x + threadIdx.x;
    if (e < N_EDGES) atomicAdd(&g_cnt[edge_index[N_EDGES + e]], 1);
}
#define SCAN_T 1024
#define SCAN_C 49   // 1024*49 = 50176 >= 50000
__global__ __launch_bounds__(SCAN_T) void k_scan()
{
    __shared__ int sh[SCAN_T];
    const int t = threadIdx.x;
    const int base = t * SCAN_C;
    int s = 0;
    #pragma unroll 4
    for (int j = 0; j < SCAN_C; j++) {
        int idx = base + j;
        if (idx < N_NODES) s += g_cnt[idx];
    }
    sh[t] = s;
    __syncthreads();
    for (int off = 1; off < SCAN_T; off <<= 1) {
        int v = (t >= off) ? sh[t - off] : 0;
        __syncthreads();
        sh[t] += v;
        __syncthreads();
    }
    int run = sh[t] - s;  // exclusive prefix
    for (int j = 0; j < SCAN_C; j++) {
        int idx = base + j;
        if (idx < N_NODES) {
            int c = g_cnt[idx];
            g_cnt[idx] = run;
            g_cur[idx] = run;
            run += c;
        }
    }
    if (t == 0) g_cnt[N_NODES] = N_EDGES;
}
__global__ __launch_bounds__(256) void k_fill(
    const int* __restrict__ edge_index, const float* __restrict__ ew)
{
    int e = blockIdx.x * blockDim.x + threadIdx.x;
    if (e >= N_EDGES) return;
    int dst = edge_index[N_EDGES + e];
    int pos = atomicAdd(&g_cur[dst], 1);
    g_esrc[pos] = edge_index[e];
    g_ewt[pos]  = ew[e];
}

// ---------------------------------------------------------------------------
// Gather (no atomics): acc = lin_part[n] + sum_e w_e * h2_part[src_e].
// hw row n = [h2 (512 fp16) | agg_lin (512 fp16)].
// 2 nodes per 128-thread block; each thread owns one 16B chunk (8 halves).
// ---------------------------------------------------------------------------
__global__ __launch_bounds__(128) void gather_nodes(
    const __half* __restrict__ hw, __half* __restrict__ aggh)
{
    const int n = blockIdx.x * 2 + (threadIdx.x >> 6);
    const int t = threadIdx.x & 63;        // 16B chunk within the 512-half row
    const int c = t * 8;                   // half index 0..504
    const int beg = g_cnt[n], end = g_cnt[n + 1];

    float acc[8];
    {   // base = lin part (cols 512..1023)
        uint4 bv = *reinterpret_cast<const uint4*>(hw + (long long)n * CLW + EMBP + c);
        const __half2* hb = reinterpret_cast<const __half2*>(&bv);
        #pragma unroll
        for (int j = 0; j < 4; j++) {
            float2 f = __half22float2(hb[j]);
            acc[j * 2] = f.x; acc[j * 2 + 1] = f.y;
        }
    }

    int e = beg;
    for (; e + 3 < end; e += 4) {
        int   s0 = g_esrc[e],   s1 = g_esrc[e+1], s2 = g_esrc[e+2], s3 = g_esrc[e+3];
        float w0 = g_ewt[e],    w1 = g_ewt[e+1],  w2 = g_ewt[e+2],  w3 = g_ewt[e+3];
        uint4 v0 = *reinterpret_cast<const uint4*>(hw + (long long)s0 * CLW + c);
        uint4 v1 = *reinterpret_cast<const uint4*>(hw + (long long)s1 * CLW + c);
        uint4 v2 = *reinterpret_cast<const uint4*>(hw + (long long)s2 * CLW + c);
        uint4 v3 = *reinterpret_cast<const uint4*>(hw + (long long)s3 * CLW + c);
        const __half2* h0 = reinterpret_cast<const __half2*>(&v0);
        const __half2* h1 = reinterpret_cast<const __half2*>(&v1);
        const __half2* h2 = reinterpret_cast<const __half2*>(&v2);
        const __half2* h3 = reinterpret_cast<const __half2*>(&v3);
        #pragma unroll
        for (int j = 0; j < 4; j++) {
            float2 f;
            f = __half22float2(h0[j]);
            acc[j*2] = fmaf(f.x, w0, acc[j*2]); acc[j*2+1] = fmaf(f.y, w0, acc[j*2+1]);
            f = __half22float2(h1[j]);
            acc[j*2] = fmaf(f.x, w1, acc[j*2]); acc[j*2+1] = fmaf(f.y, w1, acc[j*2+1]);
            f = __half22float2(h2[j]);
            acc[j*2] = fmaf(f.x, w2, acc[j*2]); acc[j*2+1] = fmaf(f.y, w2, acc[j*2+1]);
            f = __half22float2(h3[j]);
            acc[j*2] = fmaf(f.x, w3, acc[j*2]); acc[j*2+1] = fmaf(f.y, w3, acc[j*2+1]);
        }
    }
    for (; e < end; e++) {
        int   s0 = g_esrc[e];
        float w0 = g_ewt[e];
        uint4 v0 = *reinterpret_cast<const uint4*>(hw + (long long)s0 * CLW + c);
        const __half2* h0 = reinterpret_cast<const __half2*>(&v0);
        #pragma unroll
        for (int j = 0; j < 4; j++) {
            float2 f = __half22float2(h0[j]);
            acc[j*2] = fmaf(f.x, w0, acc[j*2]); acc[j*2+1] = fmaf(f.y, w0, acc[j*2+1]);
        }
    }

    uint4 ov;
    __half2* oh = reinterpret_cast<__half2*>(&ov);
    #pragma unroll
    for (int j = 0; j < 4; j++)
        oh[j] = __floats2half2_rn(acc[j * 2], acc[j * 2 + 1]);
    *reinterpret_cast<uint4*>(aggh + (long long)n * EMBP + c) = ov;
}

// ---------------------------------------------------------------------------
// Single-term fp16 GEMM, mma.sync m16n8k16 + cp.async 4-stage pipeline.
// C[M,N] = act(A[M,K] @ B[N,K]^T + bias). BM=BN=128, BK=32, 256 thr, 2 CTA/SM.
// smem rows padded to 40 halves (80B stride; conflict-free ldmatrix).
// OMODE: 0 = fp32 out, 2 = fp16 out. K mult of 32 (nk >= 16), B rows padded.
// ---------------------------------------------------------------------------
#define KPAD 40
#define TILE_BYTES (128 * KPAD * 2)        // 10240 per matrix
#define STAGE_BYTES (2 * TILE_BYTES)       // 20480
#define NSTAGE 4
#define DYNSMEM (NSTAGE * STAGE_BYTES)     // 81920 -> 2 CTAs/SM

__device__ __forceinline__ void ldsm4(uint32_t (&r)[4], uint32_t addr) {
    asm volatile("ldmatrix.sync.aligned.m8n8.x4.shared.b16 {%0,%1,%2,%3}, [%4];"
                 : "=r"(r[0]), "=r"(r[1]), "=r"(r[2]), "=r"(r[3]) : "r"(addr));
}
__device__ __forceinline__ void mma_f16(float (&c)[4], const uint32_t (&a)[4],
                                        uint32_t b0, uint32_t b1) {
    asm volatile(
        "mma.sync.aligned.m16n8k16.row.col.f32.f16.f16.f32 "
        "{%0,%1,%2,%3}, {%4,%5,%6,%7}, {%8,%9}, {%0,%1,%2,%3};"
        : "+f"(c[0]), "+f"(c[1]), "+f"(c[2]), "+f"(c[3])
        : "r"(a[0]), "r"(a[1]), "r"(a[2]), "r"(a[3]), "r"(b0), "r"(b1));
}
__device__ __forceinline__ void cpa16(uint32_t dst, const void* src, int sz) {
    asm volatile("cp.async.cg.shared.global [%0], [%1], 16, %2;"
                 :: "r"(dst), "l"(src), "r"(sz) : "memory");
}
__device__ __forceinline__ void cpa16u(uint32_t dst, const void* src) {
    asm volatile("cp.async.cg.shared.global [%0], [%1], 16;"
                 :: "r"(dst), "l"(src) : "memory");
}

template <int OMODE, bool BIAS, bool SIG>
__global__ __launch_bounds__(256, 2) void hgemm(
    const __half* __restrict__ A, int sA_,
    const __half* __restrict__ B, int sB_,
    const float* __restrict__ bias,
    float* __restrict__ C, __half* __restrict__ Ch, int sC,
    int M, int Nreal, int K)
{
    extern __shared__ char smem[];

    const int tid  = threadIdx.x;
    const int lane = tid & 31;
    const int warp = tid >> 5;
    const int wm = warp >> 1;   // 0..3
    const int wn = warp & 1;    // 0..1
    const int m0 = blockIdx.y * 128;
    const int n0 = blockIdx.x * 128;

    const int lrow = tid >> 1;
    const int cp0  = (tid & 1) * 2;
    const int gmA  = m0 + lrow;
    const int szA  = (gmA < M) ? 16 : 0;
    const __half* srcA = A + (long long)gmA * sA_ + cp0 * 8;
    const __half* srcB = B + (long long)(n0 + lrow) * sB_ + cp0 * 8;
    const uint32_t smem_u = (uint32_t)__cvta_generic_to_shared(smem);
    const uint32_t dRow = (uint32_t)(lrow * (KPAD * 2) + cp0 * 16);

    float acc[2][8][4];
    #pragma unroll
    for (int i = 0; i < 2; i++)
        #pragma unroll
        for (int j = 0; j < 8; j++)
            #pragma unroll
            for (int e = 0; e < 4; e++) acc[i][j][e] = 0.f;

    const int g = lane >> 3, r8 = lane & 7;
    const int nk = K / 32;

    auto load_stage = [&](int st, int k0) {
        const uint32_t aBase = smem_u + st * STAGE_BYTES + dRow;
        const uint32_t bBase = aBase + TILE_BYTES;
        cpa16(aBase,      srcA + k0, szA);
        cpa16(aBase + 16, srcA + k0 + 8, szA);
        cpa16u(bBase,      srcB + k0);
        cpa16u(bBase + 16, srcB + k0 + 8);
        asm volatile("cp.async.commit_group;" ::: "memory");
    };

    // prologue: 3 stages in flight (nk >= 16 always)
    load_stage(0, 0);
    load_stage(1, 32);
    load_stage(2, 64);

    const int aRowBase = wm * 32 + (g & 1) * 8 + r8;
    const int aColB    = (g >> 1) * 16;
    const int bRowBase = wn * 64 + (g >> 1) * 8 + r8;
    const int bColB    = (g & 1) * 16;

    for (int s = 0; s < nk; s++) {
        const int rem = nk - 1 - s;
        if (rem >= 2)      { asm volatile("cp.async.wait_group 2;" ::: "memory"); }
        else if (rem == 1) { asm volatile("cp.async.wait_group 1;" ::: "memory"); }
        else               { asm volatile("cp.async.wait_group 0;" ::: "memory"); }
        __syncthreads();   // stage s visible; all warps done with stage s-1 reads
        if (s + 3 < nk) load_stage((s + 3) % NSTAGE, (s + 3) * 32);

        const uint32_t aBuf = smem_u + (s % NSTAGE) * STAGE_BYTES;
        const uint32_t bBuf = aBuf + TILE_BYTES;

        #pragma unroll
        for (int ks = 0; ks < 2; ks++) {
            const int kkB = ks * 32;
            uint32_t a[2][4];
            #pragma unroll
            for (int mt = 0; mt < 2; mt++)
                ldsm4(a[mt], aBuf + (uint32_t)((aRowBase + mt * 16) * (KPAD * 2)
                                               + kkB + aColB));
            #pragma unroll
            for (int p = 0; p < 4; p++) {
                uint32_t b[4];
                ldsm4(b, bBuf + (uint32_t)((bRowBase + p * 16) * (KPAD * 2)
                                           + kkB + bColB));
                #pragma unroll
                for (int sx = 0; sx < 2; sx++)
                    #pragma unroll
                    for (int mt = 0; mt < 2; mt++)
                        mma_f16(acc[mt][p * 2 + sx], a[mt],
                                b[sx * 2], b[sx * 2 + 1]);
            }
        }
    }

    // ---- epilogue: packed stores (e-pairs are adjacent columns) ----
    const int rq = lane >> 2, cq = (lane & 3) * 2;
    #pragma unroll
    for (int mt = 0; mt < 2; mt++)
        #pragma unroll
        for (int nt = 0; nt < 8; nt++) {
            const int gc = n0 + wn * 64 + nt * 8 + cq;   // even
            #pragma unroll
            for (int half_ : {0, 1}) {
                const int gm = m0 + wm * 32 + mt * 16 + rq + half_ * 8;
                if (gm >= M) continue;
                float v0 = acc[mt][nt][half_ * 2 + 0];
                float v1 = acc[mt][nt][half_ * 2 + 1];
                if (BIAS || SIG) {
                    if (gc < Nreal)     { if (BIAS) v0 += bias[gc]; }
                    else v0 = 0.f;
                    if (gc + 1 < Nreal) { if (BIAS) v1 += bias[gc + 1]; }
                    else v1 = 0.f;
                    if (SIG) {
                        if (gc < Nreal)     v0 = 1.f / (1.f + expf(-v0));
                        if (gc + 1 < Nreal) v1 = 1.f / (1.f + expf(-v1));
                    }
                }
                if (OMODE == 2) {
                    *reinterpret_cast<__half2*>(Ch + (long long)gm * sC + gc)
                        = __floats2half2_rn(v0, v1);
                } else {
                    *reinterpret_cast<float2*>(C + (long long)gm * sC + gc)
                        = make_float2(v0, v1);
                }
            }
        }
}

// ---------------------------------------------------------------------------
extern "C" void kernel_launch(void* const* d_in, const int* in_sizes, int n_in,
                              void* d_out, int out_size)
{
    const float* x           = (const float*)d_in[0];
    const int*   edge_index  = (const int*)  d_in[1];
    const float* edge_weight = (const float*)d_in[2];
    const float* wenc        = (const float*)d_in[3];  // [EMB, IN_SIZE]
    const float* benc        = (const float*)d_in[4];
    const float* wdec        = (const float*)d_in[5];  // [IN_SIZE, EMB]
    const float* bdec        = (const float*)d_in[6];
    const float* conv_weight = (const float*)d_in[7];  // [EMB, EMB] (k, n)
    const float* lin_weight  = (const float*)d_in[8];  // [EMB, EMB] (n, k)
    float* out = (float*)d_out;

    __half *xh, *h, *hw, *aggh, *wench, *clh, *wdech;
    cudaGetSymbolAddress((void**)&xh, g_xh);
    cudaGetSymbolAddress((void**)&h, g_h);
    cudaGetSymbolAddress((void**)&hw, g_hw);
    cudaGetSymbolAddress((void**)&aggh, g_aggh);
    cudaGetSymbolAddress((void**)&wench, g_wench);
    cudaGetSymbolAddress((void**)&clh, g_clh);
    cudaGetSymbolAddress((void**)&wdech, g_wdech);

    cudaFuncSetAttribute(hgemm<2, true,  true >, cudaFuncAttributeMaxDynamicSharedMemorySize, DYNSMEM);
    cudaFuncSetAttribute(hgemm<2, false, false>, cudaFuncAttributeMaxDynamicSharedMemorySize, DYNSMEM);
    cudaFuncSetAttribute(hgemm<0, true,  false>, cudaFuncAttributeMaxDynamicSharedMemorySize, DYNSMEM);

    const int mt = (N_NODES + 127) / 128;  // 391

    // ---- prep converts (launch indices 0..4; encoder GEMM lands at 5 for ncu)
    {
        long long n4 = (long long)N_NODES * IN_SIZE / 4;
        convert_x_kernel<<<(unsigned)((n4 + 255) / 256), 256>>>((const float4*)x, xh, n4);
    }
    convert_w_kernel<false><<<(EMBP * IN_SIZE + 255) / 256, 256>>>(
        wenc, wench, EMB, IN_SIZE, EMBP, IN_SIZE);
    convert_w_kernel<true><<<(EMBP * EMBP + 255) / 256, 256>>>(
        conv_weight, clh, EMB, EMB, EMBP, EMBP);
    convert_w_kernel<false><<<(EMBP * EMBP + 255) / 256, 256>>>(
        lin_weight, clh + (size_t)EMBP * EMBP, EMB, EMB, EMBP, EMBP);
    convert_w_kernel<false><<<(IN_SIZE * EMBP + 255) / 256, 256>>>(
        wdec, wdech, IN_SIZE, EMB, IN_SIZE, EMBP);

    // 1) h = sigmoid(x @ wenc^T + benc) -> fp16       [launch #5 -> ncu target]
    {
        dim3 grid(EMBP / 128, mt);
        hgemm<2, true, true><<<grid, 256, DYNSMEM>>>(
            xh, IN_SIZE, wench, IN_SIZE, benc,
            nullptr, h, EMBP, N_NODES, EMB, IN_SIZE);
    }
    // 2) hw = h @ [conv^T ; lin]^T -> [h2 | agg_lin] fp16
    {
        dim3 grid(CLW / 128, mt);
        hgemm<2, false, false><<<grid, 256, DYNSMEM>>>(
            h, EMBP, clh, EMBP, nullptr,
            nullptr, hw, CLW, N_NODES, CLW, EMBP);
    }
    // ---- CSR build (only needed before gather) ----
    k_zero_cnt<<<(N_NODES + 1 + 255) / 256, 256>>>();
    k_count<<<(N_EDGES + 255) / 256, 256>>>(edge_index);
    k_scan<<<1, SCAN_T>>>();
    k_fill<<<(N_EDGES + 255) / 256, 256>>>(edge_index, edge_weight);

    // 3) gather (CSR, no atomics) -> aggh fp16
    gather_nodes<<<N_NODES / 2, 128>>>(hw, aggh);
    // 4) out = aggh @ wdec^T + bdec (fp32)
    {
        dim3 grid(IN_SIZE / 128, mt);
        hgemm<0, true, false><<<grid, 256, DYNSMEM>>>(
            aggh, EMBP, wdech, EMBP, bdec,
            out, nullptr, IN_SIZE, N_NODES, IN_SIZE, EMBP);
    }
}

// round 14
// speedup vs baseline: 6.3438x; 1.0938x over previous
#include <cuda_runtime.h>
#include <cuda_fp16.h>
#include <cstdint>

#define N_NODES 50000
#define N_EDGES 800000
#define IN_SIZE 1024
#define EMB 500
#define EMBP 512
#define CLW 1024   // combined conv|lin output width

// ---------------------------------------------------------------------------
// Scratch (device globals: allocation-free per harness rules)
// ---------------------------------------------------------------------------
__device__ __half g_xh[(size_t)N_NODES * IN_SIZE];     // x -> fp16
__device__ __half g_h[(size_t)N_NODES * EMBP];         // sigmoid(enc) fp16
__device__ __half g_hw[(size_t)N_NODES * CLW];         // [h2 | agg_lin] fp16
__device__ __half g_aggh[(size_t)N_NODES * EMBP];      // final agg fp16
// fp16 weights, padded [NP][Kp], K contiguous
__device__ __half g_wench[EMBP * IN_SIZE];
__device__ __half g_clh[CLW * EMBP];                   // [conv^T ; lin] stacked
__device__ __half g_wdech[IN_SIZE * EMBP];
// CSR scratch
__device__ int   g_cnt[N_NODES + 1];
__device__ int   g_cur[N_NODES];
__device__ int   g_esrc[N_EDGES];
__device__ float g_ewt[N_EDGES];

// ---------------------------------------------------------------------------
// Convert kernels
// ---------------------------------------------------------------------------
__global__ __launch_bounds__(256) void convert_x_kernel(
    const float4* __restrict__ x, __half* __restrict__ xh, long long n4)
{
    long long i = (long long)blockIdx.x * blockDim.x + threadIdx.x;
    if (i >= n4) return;
    float4 v = x[i];
    __half2* p = reinterpret_cast<__half2*>(xh) + i * 2;
    p[0] = __floats2half2_rn(v.x, v.y);
    p[1] = __floats2half2_rn(v.z, v.w);
}

template <bool TRANS>
__global__ __launch_bounds__(256) void convert_w_kernel(
    const float* __restrict__ src, __half* __restrict__ dst,
    int N, int K, int NP, int Kp)
{
    int idx = blockIdx.x * blockDim.x + threadIdx.x;
    if (idx >= NP * Kp) return;
    int n = idx / Kp, k = idx - n * Kp;
    float v = 0.f;
    if (n < N && k < K)
        v = TRANS ? src[(long long)k * N + n] : src[(long long)n * K + k];
    dst[idx] = __float2half_rn(v);
}

// ---------------------------------------------------------------------------
// CSR build kernels
// ---------------------------------------------------------------------------
__global__ __launch_bounds__(256) void k_zero_cnt()
{
    int i = blockIdx.x * blockDim.x + threadIdx.x;
    if (i <= N_NODES) g_cnt[i] = 0;
}
__global__ __launch_bounds__(256) void k_count(const int* __restrict__ edge_index)
{
    int e = blockIdx.x * blockDim.x + threadIdx.x;
    if (e < N_EDGES) atomicAdd(&g_cnt[edge_index[N_EDGES + e]], 1);
}
#define SCAN_T 1024
#define SCAN_C 49   // 1024*49 = 50176 >= 50000
__global__ __launch_bounds__(SCAN_T) void k_scan()
{
    __shared__ int sh[SCAN_T];
    const int t = threadIdx.x;
    const int base = t * SCAN_C;
    int s = 0;
    #pragma unroll 4
    for (int j = 0; j < SCAN_C; j++) {
        int idx = base + j;
        if (idx < N_NODES) s += g_cnt[idx];
    }
    sh[t] = s;
    __syncthreads();
    for (int off = 1; off < SCAN_T; off <<= 1) {
        int v = (t >= off) ? sh[t - off] : 0;
        __syncthreads();
        sh[t] += v;
        __syncthreads();
    }
    int run = sh[t] - s;  // exclusive prefix
    for (int j = 0; j < SCAN_C; j++) {
        int idx = base + j;
        if (idx < N_NODES) {
            int c = g_cnt[idx];
            g_cnt[idx] = run;
            g_cur[idx] = run;
            run += c;
        }
    }
    if (t == 0) g_cnt[N_NODES] = N_EDGES;
}
__global__ __launch_bounds__(256) void k_fill(
    const int* __restrict__ edge_index, const float* __restrict__ ew)
{
    int e = blockIdx.x * blockDim.x + threadIdx.x;
    if (e >= N_EDGES) return;
    int dst = edge_index[N_EDGES + e];
    int pos = atomicAdd(&g_cur[dst], 1);
    g_esrc[pos] = edge_index[e];
    g_ewt[pos]  = ew[e];
}

// ---------------------------------------------------------------------------
// Gather (no atomics): acc = lin_part[n] + sum_e w_e * h2_part[src_e].
// hw row n = [h2 (512 fp16) | agg_lin (512 fp16)].
// 2 nodes per 128-thread block; each thread owns one 16B chunk (8 halves).
// ---------------------------------------------------------------------------
__global__ __launch_bounds__(128) void gather_nodes(
    const __half* __restrict__ hw, __half* __restrict__ aggh)
{
    const int n = blockIdx.x * 2 + (threadIdx.x >> 6);
    const int t = threadIdx.x & 63;        // 16B chunk within the 512-half row
    const int c = t * 8;                   // half index 0..504
    const int beg = g_cnt[n], end = g_cnt[n + 1];

    float acc[8];
    {   // base = lin part (cols 512..1023)
        uint4 bv = *reinterpret_cast<const uint4*>(hw + (long long)n * CLW + EMBP + c);
        const __half2* hb = reinterpret_cast<const __half2*>(&bv);
        #pragma unroll
        for (int j = 0; j < 4; j++) {
            float2 f = __half22float2(hb[j]);
            acc[j * 2] = f.x; acc[j * 2 + 1] = f.y;
        }
    }

    int e = beg;
    for (; e + 3 < end; e += 4) {
        int   s0 = g_esrc[e],   s1 = g_esrc[e+1], s2 = g_esrc[e+2], s3 = g_esrc[e+3];
        float w0 = g_ewt[e],    w1 = g_ewt[e+1],  w2 = g_ewt[e+2],  w3 = g_ewt[e+3];
        uint4 v0 = *reinterpret_cast<const uint4*>(hw + (long long)s0 * CLW + c);
        uint4 v1 = *reinterpret_cast<const uint4*>(hw + (long long)s1 * CLW + c);
        uint4 v2 = *reinterpret_cast<const uint4*>(hw + (long long)s2 * CLW + c);
        uint4 v3 = *reinterpret_cast<const uint4*>(hw + (long long)s3 * CLW + c);
        const __half2* h0 = reinterpret_cast<const __half2*>(&v0);
        const __half2* h1 = reinterpret_cast<const __half2*>(&v1);
        const __half2* h2 = reinterpret_cast<const __half2*>(&v2);
        const __half2* h3 = reinterpret_cast<const __half2*>(&v3);
        #pragma unroll
        for (int j = 0; j < 4; j++) {
            float2 f;
            f = __half22float2(h0[j]);
            acc[j*2] = fmaf(f.x, w0, acc[j*2]); acc[j*2+1] = fmaf(f.y, w0, acc[j*2+1]);
            f = __half22float2(h1[j]);
            acc[j*2] = fmaf(f.x, w1, acc[j*2]); acc[j*2+1] = fmaf(f.y, w1, acc[j*2+1]);
            f = __half22float2(h2[j]);
            acc[j*2] = fmaf(f.x, w2, acc[j*2]); acc[j*2+1] = fmaf(f.y, w2, acc[j*2+1]);
            f = __half22float2(h3[j]);
            acc[j*2] = fmaf(f.x, w3, acc[j*2]); acc[j*2+1] = fmaf(f.y, w3, acc[j*2+1]);
        }
    }
    for (; e < end; e++) {
        int   s0 = g_esrc[e];
        float w0 = g_ewt[e];
        uint4 v0 = *reinterpret_cast<const uint4*>(hw + (long long)s0 * CLW + c);
        const __half2* h0 = reinterpret_cast<const __half2*>(&v0);
        #pragma unroll
        for (int j = 0; j < 4; j++) {
            float2 f = __half22float2(h0[j]);
            acc[j*2] = fmaf(f.x, w0, acc[j*2]); acc[j*2+1] = fmaf(f.y, w0, acc[j*2+1]);
        }
    }

    uint4 ov;
    __half2* oh = reinterpret_cast<__half2*>(&ov);
    #pragma unroll
    for (int j = 0; j < 4; j++)
        oh[j] = __floats2half2_rn(acc[j * 2], acc[j * 2 + 1]);
    *reinterpret_cast<uint4*>(aggh + (long long)n * EMBP + c) = ov;
}

// ---------------------------------------------------------------------------
// Single-term fp16 GEMM, mma.sync m16n8k16 + cp.async 4-stage pipeline.
// C[M,N] = act(A[M,K] @ B[N,K]^T + bias). BM=BN=128, BK=32, 256 thr, 2 CTA/SM.
// smem rows padded to 40 halves (80B stride; conflict-free ldmatrix).
// OMODE: 0 = fp32 out, 2 = fp16 out. K mult of 32 (nk >= 16), B rows padded.
// ---------------------------------------------------------------------------
#define KPAD 40
#define TILE_BYTES (128 * KPAD * 2)        // 10240 per matrix
#define STAGE_BYTES (2 * TILE_BYTES)       // 20480
#define NSTAGE 4
#define DYNSMEM (NSTAGE * STAGE_BYTES)     // 81920 -> 2 CTAs/SM

__device__ __forceinline__ void ldsm4(uint32_t (&r)[4], uint32_t addr) {
    asm volatile("ldmatrix.sync.aligned.m8n8.x4.shared.b16 {%0,%1,%2,%3}, [%4];"
                 : "=r"(r[0]), "=r"(r[1]), "=r"(r[2]), "=r"(r[3]) : "r"(addr));
}
__device__ __forceinline__ void mma_f16(float (&c)[4], const uint32_t (&a)[4],
                                        uint32_t b0, uint32_t b1) {
    asm volatile(
        "mma.sync.aligned.m16n8k16.row.col.f32.f16.f16.f32 "
        "{%0,%1,%2,%3}, {%4,%5,%6,%7}, {%8,%9}, {%0,%1,%2,%3};"
        : "+f"(c[0]), "+f"(c[1]), "+f"(c[2]), "+f"(c[3])
        : "r"(a[0]), "r"(a[1]), "r"(a[2]), "r"(a[3]), "r"(b0), "r"(b1));
}
__device__ __forceinline__ void cpa16(uint32_t dst, const void* src, int sz) {
    asm volatile("cp.async.cg.shared.global [%0], [%1], 16, %2;"
                 :: "r"(dst), "l"(src), "r"(sz) : "memory");
}
__device__ __forceinline__ void cpa16u(uint32_t dst, const void* src) {
    asm volatile("cp.async.cg.shared.global [%0], [%1], 16;"
                 :: "r"(dst), "l"(src) : "memory");
}

template <int OMODE, bool BIAS, bool SIG>
__global__ __launch_bounds__(256, 2) void hgemm(
    const __half* __restrict__ A, int sA_,
    const __half* __restrict__ B, int sB_,
    const float* __restrict__ bias,
    float* __restrict__ C, __half* __restrict__ Ch, int sC,
    int M, int Nreal, int K)
{
    extern __shared__ char smem[];

    const int tid  = threadIdx.x;
    const int lane = tid & 31;
    const int warp = tid >> 5;
    const int wm = warp >> 1;   // 0..3
    const int wn = warp & 1;    // 0..1
    const int m0 = blockIdx.y * 128;
    const int n0 = blockIdx.x * 128;

    const int lrow = tid >> 1;
    const int cp0  = (tid & 1) * 2;
    const int gmA  = m0 + lrow;
    const int szA  = (gmA < M) ? 16 : 0;
    const __half* srcA = A + (long long)gmA * sA_ + cp0 * 8;
    const __half* srcB = B + (long long)(n0 + lrow) * sB_ + cp0 * 8;
    const uint32_t smem_u = (uint32_t)__cvta_generic_to_shared(smem);
    const uint32_t dRow = (uint32_t)(lrow * (KPAD * 2) + cp0 * 16);

    float acc[2][8][4];
    #pragma unroll
    for (int i = 0; i < 2; i++)
        #pragma unroll
        for (int j = 0; j < 8; j++)
            #pragma unroll
            for (int e = 0; e < 4; e++) acc[i][j][e] = 0.f;

    const int g = lane >> 3, r8 = lane & 7;
    const int nk = K / 32;

    auto load_stage = [&](int st, int k0) {
        const uint32_t aBase = smem_u + st * STAGE_BYTES + dRow;
        const uint32_t bBase = aBase + TILE_BYTES;
        cpa16(aBase,      srcA + k0, szA);
        cpa16(aBase + 16, srcA + k0 + 8, szA);
        cpa16u(bBase,      srcB + k0);
        cpa16u(bBase + 16, srcB + k0 + 8);
        asm volatile("cp.async.commit_group;" ::: "memory");
    };

    // prologue: 3 stages in flight (nk >= 16 always)
    load_stage(0, 0);
    load_stage(1, 32);
    load_stage(2, 64);

    const int aRowBase = wm * 32 + (g & 1) * 8 + r8;
    const int aColB    = (g >> 1) * 16;
    const int bRowBase = wn * 64 + (g >> 1) * 8 + r8;
    const int bColB    = (g & 1) * 16;

    for (int s = 0; s < nk; s++) {
        const int rem = nk - 1 - s;
        if (rem >= 2)      { asm volatile("cp.async.wait_group 2;" ::: "memory"); }
        else if (rem == 1) { asm volatile("cp.async.wait_group 1;" ::: "memory"); }
        else               { asm volatile("cp.async.wait_group 0;" ::: "memory"); }
        __syncthreads();   // stage s visible; all warps done with stage s-1 reads
        if (s + 3 < nk) load_stage((s + 3) % NSTAGE, (s + 3) * 32);

        const uint32_t aBuf = smem_u + (s % NSTAGE) * STAGE_BYTES;
        const uint32_t bBuf = aBuf + TILE_BYTES;

        #pragma unroll
        for (int ks = 0; ks < 2; ks++) {
            const int kkB = ks * 32;
            uint32_t a[2][4];
            #pragma unroll
            for (int mt = 0; mt < 2; mt++)
                ldsm4(a[mt], aBuf + (uint32_t)((aRowBase + mt * 16) * (KPAD * 2)
                                               + kkB + aColB));
            #pragma unroll
            for (int p = 0; p < 4; p++) {
                uint32_t b[4];
                ldsm4(b, bBuf + (uint32_t)((bRowBase + p * 16) * (KPAD * 2)
                                           + kkB + bColB));
                #pragma unroll
                for (int sx = 0; sx < 2; sx++)
                    #pragma unroll
                    for (int mt = 0; mt < 2; mt++)
                        mma_f16(acc[mt][p * 2 + sx], a[mt],
                                b[sx * 2], b[sx * 2 + 1]);
            }
        }
    }

    // ---- epilogue: packed stores (e-pairs are adjacent columns) ----
    const int rq = lane >> 2, cq = (lane & 3) * 2;
    #pragma unroll
    for (int mt = 0; mt < 2; mt++)
        #pragma unroll
        for (int nt = 0; nt < 8; nt++) {
            const int gc = n0 + wn * 64 + nt * 8 + cq;   // even
            #pragma unroll
            for (int half_ : {0, 1}) {
                const int gm = m0 + wm * 32 + mt * 16 + rq + half_ * 8;
                if (gm >= M) continue;
                float v0 = acc[mt][nt][half_ * 2 + 0];
                float v1 = acc[mt][nt][half_ * 2 + 1];
                if (BIAS || SIG) {
                    if (gc < Nreal)     { if (BIAS) v0 += bias[gc]; }
                    else v0 = 0.f;
                    if (gc + 1 < Nreal) { if (BIAS) v1 += bias[gc + 1]; }
                    else v1 = 0.f;
                    if (SIG) {
                        if (gc < Nreal)     v0 = 1.f / (1.f + expf(-v0));
                        if (gc + 1 < Nreal) v1 = 1.f / (1.f + expf(-v1));
                    }
                }
                if (OMODE == 2) {
                    *reinterpret_cast<__half2*>(Ch + (long long)gm * sC + gc)
                        = __floats2half2_rn(v0, v1);
                } else {
                    *reinterpret_cast<float2*>(C + (long long)gm * sC + gc)
                        = make_float2(v0, v1);
                }
            }
        }
}

// ---------------------------------------------------------------------------
extern "C" void kernel_launch(void* const* d_in, const int* in_sizes, int n_in,
                              void* d_out, int out_size)
{
    const float* x           = (const float*)d_in[0];
    const int*   edge_index  = (const int*)  d_in[1];
    const float* edge_weight = (const float*)d_in[2];
    const float* wenc        = (const float*)d_in[3];  // [EMB, IN_SIZE]
    const float* benc        = (const float*)d_in[4];
    const float* wdec        = (const float*)d_in[5];  // [IN_SIZE, EMB]
    const float* bdec        = (const float*)d_in[6];
    const float* conv_weight = (const float*)d_in[7];  // [EMB, EMB] (k, n)
    const float* lin_weight  = (const float*)d_in[8];  // [EMB, EMB] (n, k)
    float* out = (float*)d_out;

    __half *xh, *h, *hw, *aggh, *wench, *clh, *wdech;
    cudaGetSymbolAddress((void**)&xh, g_xh);
    cudaGetSymbolAddress((void**)&h, g_h);
    cudaGetSymbolAddress((void**)&hw, g_hw);
    cudaGetSymbolAddress((void**)&aggh, g_aggh);
    cudaGetSymbolAddress((void**)&wench, g_wench);
    cudaGetSymbolAddress((void**)&clh, g_clh);
    cudaGetSymbolAddress((void**)&wdech, g_wdech);

    cudaFuncSetAttribute(hgemm<2, true,  true >, cudaFuncAttributeMaxDynamicSharedMemorySize, DYNSMEM);
    cudaFuncSetAttribute(hgemm<2, false, false>, cudaFuncAttributeMaxDynamicSharedMemorySize, DYNSMEM);
    cudaFuncSetAttribute(hgemm<0, true,  false>, cudaFuncAttributeMaxDynamicSharedMemorySize, DYNSMEM);

    const int mt = (N_NODES + 127) / 128;  // 391

    // ---- side stream for prologue work independent of the GEMM chain ----
    // Created per call and intentionally not destroyed: destroying a stream
    // that participated in capture before EndCapture would invalidate the
    // graph. kernel_launch runs only twice (correctness + capture), so the
    // leak is 2 streams + 6 events; no device-memory allocation involved.
    cudaStream_t s2;
    cudaStreamCreateWithFlags(&s2, cudaStreamNonBlocking);
    cudaEvent_t evFork, evClh, evCsr;
    cudaEventCreateWithFlags(&evFork, cudaEventDisableTiming);
    cudaEventCreateWithFlags(&evClh,  cudaEventDisableTiming);
    cudaEventCreateWithFlags(&evCsr,  cudaEventDisableTiming);

    // fork: s2 joins the capture graph via event on the (captured) stream 0
    cudaEventRecord(evFork, 0);
    cudaStreamWaitEvent(s2, evFork, 0);

    // ---- side stream: clh converts -> evClh -> CSR chain + wdec -> evCsr ----
    convert_w_kernel<true><<<(EMBP * EMBP + 255) / 256, 256, 0, s2>>>(
        conv_weight, clh, EMB, EMB, EMBP, EMBP);
    convert_w_kernel<false><<<(EMBP * EMBP + 255) / 256, 256, 0, s2>>>(
        lin_weight, clh + (size_t)EMBP * EMBP, EMB, EMB, EMBP, EMBP);
    cudaEventRecord(evClh, s2);
    k_zero_cnt<<<(N_NODES + 1 + 255) / 256, 256, 0, s2>>>();
    k_count<<<(N_EDGES + 255) / 256, 256, 0, s2>>>(edge_index);
    k_scan<<<1, SCAN_T, 0, s2>>>();
    k_fill<<<(N_EDGES + 255) / 256, 256, 0, s2>>>(edge_index, edge_weight);
    convert_w_kernel<false><<<(IN_SIZE * EMBP + 255) / 256, 256, 0, s2>>>(
        wdec, wdech, IN_SIZE, EMB, IN_SIZE, EMBP);
    cudaEventRecord(evCsr, s2);

    // ---- main stream: converts needed by GEMM1, then the GEMM chain ----
    {
        long long n4 = (long long)N_NODES * IN_SIZE / 4;
        convert_x_kernel<<<(unsigned)((n4 + 255) / 256), 256>>>((const float4*)x, xh, n4);
    }
    convert_w_kernel<false><<<(EMBP * IN_SIZE + 255) / 256, 256>>>(
        wenc, wench, EMB, IN_SIZE, EMBP, IN_SIZE);

    // 1) h = sigmoid(x @ wenc^T + benc) -> fp16
    {
        dim3 grid(EMBP / 128, mt);
        hgemm<2, true, true><<<grid, 256, DYNSMEM>>>(
            xh, IN_SIZE, wench, IN_SIZE, benc,
            nullptr, h, EMBP, N_NODES, EMB, IN_SIZE);
    }
    // 2) hw = h @ [conv^T ; lin]^T -> [h2 | agg_lin] fp16 (needs clh)
    cudaStreamWaitEvent(0, evClh, 0);
    {
        dim3 grid(CLW / 128, mt);
        hgemm<2, false, false><<<grid, 256, DYNSMEM>>>(
            h, EMBP, clh, EMBP, nullptr,
            nullptr, hw, CLW, N_NODES, CLW, EMBP);
    }
    // 3) gather (needs CSR) -> aggh fp16
    cudaStreamWaitEvent(0, evCsr, 0);
    gather_nodes<<<N_NODES / 2, 128>>>(hw, aggh);
    // 4) out = aggh @ wdec^T + bdec (fp32)
    {
        dim3 grid(IN_SIZE / 128, mt);
        hgemm<0, true, false><<<grid, 256, DYNSMEM>>>(
            aggh, EMBP, wdech, EMBP, bdec,
            out, nullptr, IN_SIZE, N_NODES, IN_SIZE, EMBP);
    }
}